// round 2
// baseline (speedup 1.0000x reference)
#include <cuda_runtime.h>
#include <math.h>

#define TT 1024
#define BB 4
#define DD 512
#define HH 8
#define TP 1152
#define LCW 128
#define NEGINF (__int_as_float(0xff800000))

// ---------------- scratch (static device memory) ----------------
#define OFF_XPAD 0UL           // 4*1152*512  = 2359296
#define OFF_XBUF 2359296UL     // 4*1024*512  = 2097152
#define OFF_YBUF 4456448UL     // 2097152
#define OFF_QBUF 6553600UL     // 4*1152*512  = 2359296
#define OFF_KBUF 8912896UL     // 4*1152*128  = 589824
#define OFF_VBUF 9502720UL     // 589824
#define OFF_QREL 10092544UL    // 36864*383   = 14118912
#define OFF_OBUF 24211456UL    // 2097152
#define OFF_HBUF 26308608UL    // 4096*2048   = 8388608
#define OFF_GBUF 34697216UL    // 4096*1024   = 4194304
#define SCR_TOTAL 38891520UL

__device__ float g_scr[SCR_TOTAL];

// ---------------- zero the left-context pad rows of xpad ----------------
__global__ void zero_pad_kernel(float* __restrict__ xpad) {
    int i = blockIdx.x * 256 + threadIdx.x;
    if (i < BB * LCW * DD) {
        int b = i / (LCW * DD);
        int rem = i - b * (LCW * DD);
        xpad[(size_t)b * TP * DD + rem] = 0.f;
    }
}

// ---------------- LayerNorm (one block of 128 threads per 512-row) ----------------
__global__ __launch_bounds__(128) void ln_kernel(
    const float* __restrict__ x, const float* __restrict__ w,
    const float* __restrict__ bvec, float* __restrict__ out,
    float* __restrict__ outpad)
{
    __shared__ float red[8];
    int r = blockIdx.x;
    int tid = threadIdx.x;
    const float* xr = x + (size_t)r * DD;
    float4 v = *(const float4*)(xr + tid * 4);
    float s  = v.x + v.y + v.z + v.w;
    float sq = v.x * v.x + v.y * v.y + v.z * v.z + v.w * v.w;
#pragma unroll
    for (int o = 16; o > 0; o >>= 1) {
        s  += __shfl_xor_sync(0xffffffffu, s, o);
        sq += __shfl_xor_sync(0xffffffffu, sq, o);
    }
    int warp = tid >> 5;
    if ((tid & 31) == 0) { red[warp] = s; red[4 + warp] = sq; }
    __syncthreads();
    float ts = red[0] + red[1] + red[2] + red[3];
    float tq = red[4] + red[5] + red[6] + red[7];
    float mean = ts * (1.f / DD);
    float var  = tq * (1.f / DD) - mean * mean;
    float inv  = rsqrtf(var + 1e-4f);
    float4 wv = *(const float4*)(w + tid * 4);
    float4 bv = *(const float4*)(bvec + tid * 4);
    float4 o;
    o.x = (v.x - mean) * inv * wv.x + bv.x;
    o.y = (v.y - mean) * inv * wv.y + bv.y;
    o.z = (v.z - mean) * inv * wv.z + bv.z;
    o.w = (v.w - mean) * inv * wv.w + bv.w;
    *(float4*)(out + (size_t)r * DD + tid * 4) = o;
    if (outpad) {
        int b = r >> 10, t = r & 1023;
        *(float4*)(outpad + ((size_t)(b * TP + LCW + t)) * DD + tid * 4) = o;
    }
}

// ---------------- GEMM: C[M,N] = alpha * A[M,K] @ B[N,K]^T (+ Res) ----------------
// Requirements: M % 128 == 0, K % 16 == 0. N arbitrary (guarded).
__global__ __launch_bounds__(256) void gemm_abt(
    const float* __restrict__ A, const float* __restrict__ B,
    float* __restrict__ C, const float* __restrict__ Res,
    int M, int N, int K, float alpha)
{
    __shared__ float As[16 * 132];
    __shared__ float Bs[16 * 68];
    int tid = threadIdx.x;
    int bm = blockIdx.y * 128;
    int bn = blockIdx.x * 64;
    int tx = tid & 15, ty = tid >> 4;
    float acc[8][4];
#pragma unroll
    for (int i = 0; i < 8; i++)
#pragma unroll
        for (int j = 0; j < 4; j++) acc[i][j] = 0.f;

    for (int k0 = 0; k0 < K; k0 += 16) {
#pragma unroll
        for (int i = 0; i < 2; i++) {
            int f = tid + i * 256;
            int row = f >> 2, kq = f & 3;
            float4 v = *(const float4*)(A + (size_t)(bm + row) * K + k0 + kq * 4);
            As[(kq * 4 + 0) * 132 + row] = v.x;
            As[(kq * 4 + 1) * 132 + row] = v.y;
            As[(kq * 4 + 2) * 132 + row] = v.z;
            As[(kq * 4 + 3) * 132 + row] = v.w;
        }
        {
            int row = tid >> 2, kq = tid & 3;
            float4 v = make_float4(0.f, 0.f, 0.f, 0.f);
            if (bn + row < N)
                v = *(const float4*)(B + (size_t)(bn + row) * K + k0 + kq * 4);
            Bs[(kq * 4 + 0) * 68 + row] = v.x;
            Bs[(kq * 4 + 1) * 68 + row] = v.y;
            Bs[(kq * 4 + 2) * 68 + row] = v.z;
            Bs[(kq * 4 + 3) * 68 + row] = v.w;
        }
        __syncthreads();
#pragma unroll
        for (int k = 0; k < 16; k++) {
            float4 a0 = *(float4*)&As[k * 132 + ty * 8];
            float4 a1 = *(float4*)&As[k * 132 + ty * 8 + 4];
            float4 b0 = *(float4*)&Bs[k * 68 + tx * 4];
            acc[0][0] += a0.x * b0.x; acc[0][1] += a0.x * b0.y; acc[0][2] += a0.x * b0.z; acc[0][3] += a0.x * b0.w;
            acc[1][0] += a0.y * b0.x; acc[1][1] += a0.y * b0.y; acc[1][2] += a0.y * b0.z; acc[1][3] += a0.y * b0.w;
            acc[2][0] += a0.z * b0.x; acc[2][1] += a0.z * b0.y; acc[2][2] += a0.z * b0.z; acc[2][3] += a0.z * b0.w;
            acc[3][0] += a0.w * b0.x; acc[3][1] += a0.w * b0.y; acc[3][2] += a0.w * b0.z; acc[3][3] += a0.w * b0.w;
            acc[4][0] += a1.x * b0.x; acc[4][1] += a1.x * b0.y; acc[4][2] += a1.x * b0.z; acc[4][3] += a1.x * b0.w;
            acc[5][0] += a1.y * b0.x; acc[5][1] += a1.y * b0.y; acc[5][2] += a1.y * b0.z; acc[5][3] += a1.y * b0.w;
            acc[6][0] += a1.z * b0.x; acc[6][1] += a1.z * b0.y; acc[6][2] += a1.z * b0.z; acc[6][3] += a1.z * b0.w;
            acc[7][0] += a1.w * b0.x; acc[7][1] += a1.w * b0.y; acc[7][2] += a1.w * b0.z; acc[7][3] += a1.w * b0.w;
        }
        __syncthreads();
    }
#pragma unroll
    for (int i = 0; i < 8; i++) {
        int row = bm + ty * 8 + i;
#pragma unroll
        for (int j = 0; j < 4; j++) {
            int col = bn + tx * 4 + j;
            if (col < N) {
                float val = acc[i][j] * alpha;
                if (Res) val += Res[(size_t)row * N + col];
                C[(size_t)row * N + col] = val;
            }
        }
    }
}

// ---------------- Windowed attention (valid rows) ----------------
// grid (16 chunks [c=2..17], 8 heads, 4 batch), 256 threads, dyn smem.
__global__ __launch_bounds__(256) void win_attn(
    const float* __restrict__ qb, const float* __restrict__ kb,
    const float* __restrict__ vb, const float* __restrict__ qrel,
    const int* __restrict__ alen, float* __restrict__ ob)
{
    extern __shared__ float sm[];
    float* Qs = sm;                 // 64*65
    float* Ks = Qs + 64 * 65;       // 192*65
    float* Vs = Ks + 192 * 65;      // 192*65
    float* S  = Vs + 192 * 65;      // 64*193

    int c = blockIdx.x + 2;
    int h = blockIdx.y;
    int b = blockIdx.z;
    int cs = c * 64;
    int lim = alen[b] + LCW;
    if (cs >= lim) return;          // uniform predicate
    int tid = threadIdx.x;
    int g = h >> 2;

    const float* qbase = qb + ((size_t)(b * TP + cs)) * DD + h * 64;
#pragma unroll
    for (int i = 0; i < 4; i++) {
        int e = tid + i * 256;
        int row = e >> 4, dq = (e & 15) * 4;
        float4 v = *(const float4*)(qbase + (size_t)row * DD + dq);
        Qs[row * 65 + dq + 0] = v.x; Qs[row * 65 + dq + 1] = v.y;
        Qs[row * 65 + dq + 2] = v.z; Qs[row * 65 + dq + 3] = v.w;
    }
    const float* kbase = kb + ((size_t)(b * TP + cs - 128)) * 128 + g * 64;
    const float* vbase = vb + ((size_t)(b * TP + cs - 128)) * 128 + g * 64;
#pragma unroll
    for (int i = 0; i < 12; i++) {
        int e = tid + i * 256;
        int row = e >> 4, dq = (e & 15) * 4;
        float4 kv = *(const float4*)(kbase + (size_t)row * 128 + dq);
        Ks[row * 65 + dq + 0] = kv.x; Ks[row * 65 + dq + 1] = kv.y;
        Ks[row * 65 + dq + 2] = kv.z; Ks[row * 65 + dq + 3] = kv.w;
        float4 vv = *(const float4*)(vbase + (size_t)row * 128 + dq);
        Vs[row * 65 + dq + 0] = vv.x; Vs[row * 65 + dq + 1] = vv.y;
        Vs[row * 65 + dq + 2] = vv.z; Vs[row * 65 + dq + 3] = vv.w;
    }
    __syncthreads();

    int tx = tid & 15, ty = tid >> 4;
    // scores + bias + key-validity mask
#pragma unroll
    for (int rr = 0; rr < 4; rr++) {
        int r = rr * 16 + ty;
        size_t qr = ((size_t)(b * TP + cs + r) * HH + h) * 383;
#pragma unroll
        for (int jj = 0; jj < 12; jj++) {
            int j = jj * 16 + tx;
            float acc = 0.f;
#pragma unroll
            for (int d = 0; d < 64; d++) acc += Qs[r * 65 + d] * Ks[j * 65 + d];
            int kk = cs - 128 + j;
            float s = (kk < lim) ? (acc + __ldg(&qrel[qr + 319 + r - j])) : NEGINF;
            S[r * 193 + j] = s;
        }
    }
    __syncthreads();

    // softmax per row (warp per row)
    int lane = tid & 31, wid = tid >> 5;
#pragma unroll
    for (int rw = 0; rw < 8; rw++) {
        int r = rw * 8 + wid;
        float sv[6];
        float m = NEGINF;
#pragma unroll
        for (int t = 0; t < 6; t++) { sv[t] = S[r * 193 + lane + t * 32]; m = fmaxf(m, sv[t]); }
#pragma unroll
        for (int o = 16; o > 0; o >>= 1) m = fmaxf(m, __shfl_xor_sync(0xffffffffu, m, o));
        float ss = 0.f;
#pragma unroll
        for (int t = 0; t < 6; t++) { sv[t] = expf(sv[t] - m); ss += sv[t]; }
#pragma unroll
        for (int o = 16; o > 0; o >>= 1) ss += __shfl_xor_sync(0xffffffffu, ss, o);
        float inv = 1.f / ss;
#pragma unroll
        for (int t = 0; t < 6; t++) S[r * 193 + lane + t * 32] = sv[t] * inv;
    }
    __syncthreads();

    // P @ V
#pragma unroll
    for (int rr = 0; rr < 4; rr++) {
        int r = rr * 16 + ty;
        int q = cs + r;
        int d0 = tx * 4;
        float a0 = 0.f, a1 = 0.f, a2 = 0.f, a3 = 0.f;
#pragma unroll 4
        for (int j = 0; j < 192; j++) {
            float p = S[r * 193 + j];
            a0 += p * Vs[j * 65 + d0 + 0];
            a1 += p * Vs[j * 65 + d0 + 1];
            a2 += p * Vs[j * 65 + d0 + 2];
            a3 += p * Vs[j * 65 + d0 + 3];
        }
        if (q < lim) {
            float* op = ob + ((size_t)(b * TT + q - 128)) * DD + h * 64 + d0;
            op[0] = a0; op[1] = a1; op[2] = a2; op[3] = a3;
        }
    }
}

// ---------------- Dense attention (invalid rows: full 1152-key softmax) ----------------
// grid (1024, 8, 4), 128 threads. One block per (q,h,b). Early exit if row valid.
__global__ __launch_bounds__(128) void dense_attn(
    const float* __restrict__ qb, const float* __restrict__ kb,
    const float* __restrict__ vb, const float* __restrict__ qrel,
    const int* __restrict__ alen, float* __restrict__ ob)
{
    __shared__ float Kp[128 * 65];
    __shared__ float sc[TP];
    __shared__ float qv[64];
    __shared__ float red[128];
    int q = 128 + blockIdx.x;
    int h = blockIdx.y, b = blockIdx.z;
    int lim = alen[b] + 128;
    if (q < lim) return;            // uniform predicate
    int tid = threadIdx.x;
    int g = h >> 2;
    if (tid < 64) qv[tid] = qb[((size_t)(b * TP + q)) * DD + h * 64 + tid];
    size_t qr = ((size_t)(b * TP + q) * HH + h) * 383;

    for (int pg = 0; pg < 9; pg++) {
#pragma unroll
        for (int i = 0; i < 16; i++) {
            int e = tid + i * 128;
            int row = e >> 4, dq = (e & 15) * 4;
            float4 v = *(const float4*)(kb + ((size_t)(b * TP + pg * 128 + row)) * 128 + g * 64 + dq);
            Kp[row * 65 + dq + 0] = v.x; Kp[row * 65 + dq + 1] = v.y;
            Kp[row * 65 + dq + 2] = v.z; Kp[row * 65 + dq + 3] = v.w;
        }
        __syncthreads();
        float acc = 0.f;
#pragma unroll
        for (int d = 0; d < 64; d++) acc += qv[d] * Kp[tid * 65 + d];
        int k = pg * 128 + tid;
        int dist = q - k;
        dist = max(-191, min(191, dist));
        sc[k] = acc + __ldg(&qrel[qr + 191 + dist]);
        __syncthreads();
    }
    // softmax (unnormalized exp in sc; scale at the end)
    float lm = NEGINF;
#pragma unroll
    for (int p = 0; p < 9; p++) lm = fmaxf(lm, sc[tid + p * 128]);
    red[tid] = lm; __syncthreads();
    for (int s = 64; s > 0; s >>= 1) { if (tid < s) red[tid] = fmaxf(red[tid], red[tid + s]); __syncthreads(); }
    float m = red[0];
    __syncthreads();
    float ls = 0.f;
#pragma unroll
    for (int p = 0; p < 9; p++) { float e = expf(sc[tid + p * 128] - m); sc[tid + p * 128] = e; ls += e; }
    red[tid] = ls; __syncthreads();
    for (int s = 64; s > 0; s >>= 1) { if (tid < s) red[tid] += red[tid + s]; __syncthreads(); }
    float inv = 1.f / red[0];
    __syncthreads();
    // P @ V
    int d = tid & 63, half = tid >> 6;
    float acc = 0.f;
    for (int pg = 0; pg < 9; pg++) {
#pragma unroll
        for (int i = 0; i < 16; i++) {
            int e = tid + i * 128;
            int row = e >> 4, dq = (e & 15) * 4;
            float4 v = *(const float4*)(vb + ((size_t)(b * TP + pg * 128 + row)) * 128 + g * 64 + dq);
            Kp[row * 65 + dq + 0] = v.x; Kp[row * 65 + dq + 1] = v.y;
            Kp[row * 65 + dq + 2] = v.z; Kp[row * 65 + dq + 3] = v.w;
        }
        __syncthreads();
        int jb = half * 64;
#pragma unroll 8
        for (int jj = 0; jj < 64; jj++)
            acc += sc[pg * 128 + jb + jj] * Kp[(jb + jj) * 65 + d];
        __syncthreads();
    }
    red[tid] = acc; __syncthreads();
    if (tid < 64) {
        float o = (red[tid] + red[tid + 64]) * inv;
        ob[((size_t)(b * TT + q - 128)) * DD + h * 64 + tid] = o;
    }
}

// ---------------- GLU / SwiGLU ----------------
// mode 0: out = a * sigmoid(g)   (conv GLU)
// mode 1: out = silu(a) * g      (FFN SwiGLU)
__global__ void glu_kernel(const float* __restrict__ h, float* __restrict__ o,
                           int rows, int half4, int mode)
{
    int i = blockIdx.x * blockDim.x + threadIdx.x;
    if (i >= rows * half4) return;
    int row = i / half4, cc = i - row * half4;
    const float4* hp = (const float4*)h;
    float4 a = hp[(size_t)row * (2 * half4) + cc];
    float4 g = hp[(size_t)row * (2 * half4) + half4 + cc];
    float4 r;
    if (mode == 0) {
        r.x = a.x / (1.f + expf(-g.x));
        r.y = a.y / (1.f + expf(-g.y));
        r.z = a.z / (1.f + expf(-g.z));
        r.w = a.w / (1.f + expf(-g.w));
    } else {
        r.x = a.x / (1.f + expf(-a.x)) * g.x;
        r.y = a.y / (1.f + expf(-a.y)) * g.y;
        r.z = a.z / (1.f + expf(-a.z)) * g.z;
        r.w = a.w / (1.f + expf(-a.w)) * g.w;
    }
    ((float4*)o)[(size_t)row * half4 + cc] = r;
}

// ---------------- depthwise conv (k=9, pad 4) + SiLU ----------------
__global__ __launch_bounds__(128) void dwconv_silu(
    const float* __restrict__ in, const float* __restrict__ dw, float* __restrict__ out)
{
    int t = blockIdx.x, b = blockIdx.y;
    int d0 = threadIdx.x * 4;
    float w[9][4];
#pragma unroll
    for (int c = 0; c < 4; c++)
#pragma unroll
        for (int j = 0; j < 9; j++)
            w[j][c] = __ldg(&dw[(d0 + c) * 9 + j]);
    float4 acc = make_float4(0.f, 0.f, 0.f, 0.f);
#pragma unroll
    for (int j = 0; j < 9; j++) {
        int tt = t + j - 4;
        if (tt >= 0 && tt < TT) {
            float4 v = *(const float4*)(in + ((size_t)(b * TT + tt)) * DD + d0);
            acc.x += v.x * w[j][0];
            acc.y += v.y * w[j][1];
            acc.z += v.z * w[j][2];
            acc.w += v.w * w[j][3];
        }
    }
    acc.x = acc.x / (1.f + expf(-acc.x));
    acc.y = acc.y / (1.f + expf(-acc.y));
    acc.z = acc.z / (1.f + expf(-acc.z));
    acc.w = acc.w / (1.f + expf(-acc.w));
    *(float4*)(out + ((size_t)(b * TT + t)) * DD + d0) = acc;
}

// ---------------- orchestration ----------------
extern "C" void kernel_launch(void* const* d_in, const int* in_sizes, int n_in,
                              void* d_out, int out_size)
{
    const float* x_in  = (const float*)d_in[0];
    const int*   alen  = (const int*)d_in[1];
    const float* ln1_w = (const float*)d_in[2];
    const float* ln1_b = (const float*)d_in[3];
    const float* wq    = (const float*)d_in[4];
    const float* wk    = (const float*)d_in[5];
    const float* wv    = (const float*)d_in[6];
    const float* wo    = (const float*)d_in[7];
    const float* rel   = (const float*)d_in[8];
    const float* ln2_w = (const float*)d_in[9];
    const float* ln2_b = (const float*)d_in[10];
    const float* pw1   = (const float*)d_in[11];
    const float* dw    = (const float*)d_in[12];
    const float* pw2   = (const float*)d_in[13];
    const float* ln3_w = (const float*)d_in[14];
    const float* ln3_b = (const float*)d_in[15];
    const float* w1    = (const float*)d_in[16];
    const float* w2    = (const float*)d_in[17];

    float* scr = nullptr;
    cudaGetSymbolAddress((void**)&scr, g_scr);
    float* xpad = scr + OFF_XPAD;
    float* xbuf = scr + OFF_XBUF;
    float* ybuf = scr + OFF_YBUF;
    float* qbuf = scr + OFF_QBUF;
    float* kbuf = scr + OFF_KBUF;
    float* vbuf = scr + OFF_VBUF;
    float* qrlb = scr + OFF_QREL;
    float* obuf = scr + OFF_OBUF;
    float* hbuf = scr + OFF_HBUF;
    float* gbuf = scr + OFF_GBUF;

    const int WIN_SMEM = (64 * 65 + 192 * 65 + 192 * 65 + 64 * 193) * 4; // 165888
    cudaFuncSetAttribute(win_attn, cudaFuncAttributeMaxDynamicSharedMemorySize, WIN_SMEM);

    zero_pad_kernel<<<(BB * LCW * DD + 255) / 256, 256>>>(xpad);

    for (int l = 0; l < 4; l++) {
        const float* src = (l == 0) ? x_in : xbuf;
        // LN1 -> ybuf (residual base) + xpad (padded input for projections)
        ln_kernel<<<4096, 128>>>(src, ln1_w + l * 512, ln1_b + l * 512, ybuf, xpad);
        // Q (scaled), K, V projections over padded rows
        gemm_abt<<<dim3(8, 36), 256>>>(xpad, wq + (size_t)l * 512 * 512, qbuf, nullptr, 4608, 512, 512, 0.125f);
        gemm_abt<<<dim3(2, 36), 256>>>(xpad, wk + (size_t)l * 128 * 512, kbuf, nullptr, 4608, 128, 512, 1.f);
        gemm_abt<<<dim3(2, 36), 256>>>(xpad, wv + (size_t)l * 128 * 512, vbuf, nullptr, 4608, 128, 512, 1.f);
        // relative-position bias table: qrel = Q @ rel^T
        gemm_abt<<<dim3(6, 288), 256>>>(qbuf, rel + (size_t)l * 383 * 64, qrlb, nullptr, 36864, 383, 64, 1.f);
        // attention
        win_attn<<<dim3(16, 8, 4), 256, WIN_SMEM>>>(qbuf, kbuf, vbuf, qrlb, alen, obuf);
        dense_attn<<<dim3(1024, 8, 4), 128>>>(qbuf, kbuf, vbuf, qrlb, alen, obuf);
        // O projection + residual
        gemm_abt<<<dim3(8, 32), 256>>>(obuf, wo + (size_t)l * 512 * 512, xbuf, ybuf, 4096, 512, 512, 1.f);
        // conv module
        ln_kernel<<<4096, 128>>>(xbuf, ln2_w + l * 512, ln2_b + l * 512, ybuf, nullptr);
        gemm_abt<<<dim3(16, 32), 256>>>(ybuf, pw1 + (size_t)l * 1024 * 512, hbuf, nullptr, 4096, 1024, 512, 1.f);
        glu_kernel<<<(4096 * 128 + 255) / 256, 256>>>(hbuf, gbuf, 4096, 128, 0);
        dwconv_silu<<<dim3(1024, 4), 128>>>(gbuf, dw + (size_t)l * 512 * 9, hbuf);
        gemm_abt<<<dim3(8, 32), 256>>>(hbuf, pw2 + (size_t)l * 512 * 512, xbuf, ybuf, 4096, 512, 512, 1.f);
        // FFN
        ln_kernel<<<4096, 128>>>(xbuf, ln3_w + l * 512, ln3_b + l * 512, ybuf, nullptr);
        gemm_abt<<<dim3(32, 32), 256>>>(ybuf, w1 + (size_t)l * 2048 * 512, hbuf, nullptr, 4096, 2048, 512, 1.f);
        glu_kernel<<<(4096 * 256 + 255) / 256, 256>>>(hbuf, gbuf, 4096, 256, 1);
        float* dst = (l == 3) ? (float*)d_out : xbuf;
        gemm_abt<<<dim3(8, 32), 256>>>(gbuf, w2 + (size_t)l * 512 * 1024, dst, ybuf, 4096, 512, 1024, 1.f);
    }
}

// round 3
// speedup vs baseline: 1.3454x; 1.3454x over previous
#include <cuda_runtime.h>
#include <math.h>

#define TT 1024
#define BB 4
#define DD 512
#define HH 8
#define TP 1152
#define LCW 128
#define NEGINF (__int_as_float(0xff800000))

// ---------------- scratch (static device memory) ----------------
#define OFF_XPAD  0UL          // 4*1152*512  = 2359296
#define OFF_XBUF  2359296UL    // 2097152
#define OFF_YBUF  4456448UL    // 2097152
#define OFF_QBUF  6553600UL    // 4608*512    = 2359296
#define OFF_KVBUF 8912896UL    // 4608*256    = 1179648
#define OFF_QREL  10092544UL   // 36864*383   = 14118912
#define OFF_OBUF  24211456UL   // 2097152
#define OFF_HBUF  26308608UL   // 8388608
#define OFF_GBUF  34697216UL   // 4194304
#define OFF_KVW   38891520UL   // 4*256*512   = 524288
#define SCR_TOTAL 39415808UL

__device__ float g_scr[SCR_TOTAL];

// ---------------- zero the left-context pad rows of xpad ----------------
__global__ void zero_pad_kernel(float* __restrict__ xpad) {
    int i = blockIdx.x * 256 + threadIdx.x;
    if (i < BB * LCW * DD) {
        int b = i / (LCW * DD);
        int rem = i - b * (LCW * DD);
        xpad[(size_t)b * TP * DD + rem] = 0.f;
    }
}

// ---------------- pack K/V weights: kvw[l][256][512] ----------------
__global__ void pack_kv(const float* __restrict__ wk, const float* __restrict__ wv,
                        float* __restrict__ kvw)
{
    int i = blockIdx.x * 256 + threadIdx.x;
    if (i >= 4 * 256 * 512) return;
    int l = i / (256 * 512);
    int r = (i / 512) % 256;
    int c = i % 512;
    float v = (r < 128) ? wk[(size_t)l * 128 * 512 + r * 512 + c]
                        : wv[(size_t)l * 128 * 512 + (r - 128) * 512 + c];
    kvw[i] = v;
}

// ---------------- LayerNorm ----------------
__global__ __launch_bounds__(128) void ln_kernel(
    const float* __restrict__ x, const float* __restrict__ w,
    const float* __restrict__ bvec, float* __restrict__ out,
    float* __restrict__ outpad)
{
    __shared__ float red[8];
    int r = blockIdx.x;
    int tid = threadIdx.x;
    const float* xr = x + (size_t)r * DD;
    float4 v = *(const float4*)(xr + tid * 4);
    float s  = v.x + v.y + v.z + v.w;
    float sq = v.x * v.x + v.y * v.y + v.z * v.z + v.w * v.w;
#pragma unroll
    for (int o = 16; o > 0; o >>= 1) {
        s  += __shfl_xor_sync(0xffffffffu, s, o);
        sq += __shfl_xor_sync(0xffffffffu, sq, o);
    }
    int warp = tid >> 5;
    if ((tid & 31) == 0) { red[warp] = s; red[4 + warp] = sq; }
    __syncthreads();
    float ts = red[0] + red[1] + red[2] + red[3];
    float tq = red[4] + red[5] + red[6] + red[7];
    float mean = ts * (1.f / DD);
    float var  = tq * (1.f / DD) - mean * mean;
    float inv  = rsqrtf(var + 1e-4f);
    float4 wv = *(const float4*)(w + tid * 4);
    float4 bv = *(const float4*)(bvec + tid * 4);
    float4 o;
    o.x = (v.x - mean) * inv * wv.x + bv.x;
    o.y = (v.y - mean) * inv * wv.y + bv.y;
    o.z = (v.z - mean) * inv * wv.z + bv.z;
    o.w = (v.w - mean) * inv * wv.w + bv.w;
    *(float4*)(out + (size_t)r * DD + tid * 4) = o;
    if (outpad) {
        int b = r >> 10, t = r & 1023;
        *(float4*)(outpad + ((size_t)(b * TP + LCW + t)) * DD + tid * 4) = o;
    }
}

// ---------------- TF32 tensor-core GEMM ----------------
// C[M,N] = alpha * A[M,K] @ B[N,K]^T (+ Res). M%128==0, K%16==0, N guarded.
__device__ __forceinline__ unsigned f2tf(float x) {
    unsigned r;
    asm("cvt.rna.tf32.f32 %0, %1;" : "=r"(r) : "f"(x));
    return r;
}

__device__ __forceinline__ void mma_tf32(float* c, const unsigned* a, const unsigned* b) {
    asm volatile(
        "mma.sync.aligned.m16n8k8.row.col.f32.tf32.tf32.f32 "
        "{%0,%1,%2,%3}, {%4,%5,%6,%7}, {%8,%9}, {%0,%1,%2,%3};"
        : "+f"(c[0]), "+f"(c[1]), "+f"(c[2]), "+f"(c[3])
        : "r"(a[0]), "r"(a[1]), "r"(a[2]), "r"(a[3]), "r"(b[0]), "r"(b[1]));
}

__global__ __launch_bounds__(256) void gemm_tc(
    const float* __restrict__ A, const float* __restrict__ B,
    float* __restrict__ C, const float* __restrict__ Res,
    int M, int N, int K, float alpha)
{
    __shared__ unsigned As[2][128][20];
    __shared__ unsigned Bs[2][64][20];

    int tid = threadIdx.x;
    int bm = blockIdx.y * 128;
    int bn = blockIdx.x * 64;
    int wid = tid >> 5, lane = tid & 31;
    int wm = wid & 3, wn = wid >> 2;        // 4x2 warp grid
    int gid = lane >> 2, tig = lane & 3;

    float acc[2][4][4];
#pragma unroll
    for (int i = 0; i < 2; i++)
#pragma unroll
        for (int j = 0; j < 4; j++)
#pragma unroll
            for (int q = 0; q < 4; q++) acc[i][j][q] = 0.f;

    int arow0 = tid >> 1;                    // not used; see explicit mapping below
    (void)arow0;
    int nIters = K >> 4;

    // gmem staging registers
    float4 va[2]; float4 vb;
    int ar[2], ac[2], brow, bc;
#pragma unroll
    for (int i = 0; i < 2; i++) {
        int idx = tid + i * 256;
        ar[i] = idx >> 2;        // 0..127
        ac[i] = (idx & 3) * 4;   // 0,4,8,12
    }
    brow = tid >> 2;             // 0..63
    bc   = (tid & 3) * 4;

    // prologue: load tile 0
#pragma unroll
    for (int i = 0; i < 2; i++)
        va[i] = *(const float4*)(A + (size_t)(bm + ar[i]) * K + ac[i]);
    if (bn + brow < N) vb = *(const float4*)(B + (size_t)(bn + brow) * K + bc);
    else vb = make_float4(0.f, 0.f, 0.f, 0.f);

#pragma unroll
    for (int i = 0; i < 2; i++) {
        uint4 t = make_uint4(f2tf(va[i].x), f2tf(va[i].y), f2tf(va[i].z), f2tf(va[i].w));
        *(uint4*)&As[0][ar[i]][ac[i]] = t;
    }
    {
        uint4 t = make_uint4(f2tf(vb.x), f2tf(vb.y), f2tf(vb.z), f2tf(vb.w));
        *(uint4*)&Bs[0][brow][bc] = t;
    }
    __syncthreads();

    for (int t = 0; t < nIters; t++) {
        int cur = t & 1;
        if (t + 1 < nIters) {
            int k0 = (t + 1) << 4;
#pragma unroll
            for (int i = 0; i < 2; i++)
                va[i] = *(const float4*)(A + (size_t)(bm + ar[i]) * K + k0 + ac[i]);
            if (bn + brow < N) vb = *(const float4*)(B + (size_t)(bn + brow) * K + k0 + bc);
            else vb = make_float4(0.f, 0.f, 0.f, 0.f);
        }
        // compute from buffer cur
#pragma unroll
        for (int ks = 0; ks < 2; ks++) {
            int kk = ks * 8;
            unsigned a[2][4], b[4][2];
#pragma unroll
            for (int mt = 0; mt < 2; mt++) {
                int m0 = wm * 32 + mt * 16 + gid;
                a[mt][0] = As[cur][m0][kk + tig];
                a[mt][1] = As[cur][m0 + 8][kk + tig];
                a[mt][2] = As[cur][m0][kk + tig + 4];
                a[mt][3] = As[cur][m0 + 8][kk + tig + 4];
            }
#pragma unroll
            for (int nt = 0; nt < 4; nt++) {
                int n0 = wn * 32 + nt * 8 + gid;
                b[nt][0] = Bs[cur][n0][kk + tig];
                b[nt][1] = Bs[cur][n0][kk + tig + 4];
            }
#pragma unroll
            for (int mt = 0; mt < 2; mt++)
#pragma unroll
                for (int nt = 0; nt < 4; nt++)
                    mma_tf32(acc[mt][nt], a[mt], b[nt]);
        }
        if (t + 1 < nIters) {
            int nxt = (t + 1) & 1;
#pragma unroll
            for (int i = 0; i < 2; i++) {
                uint4 u = make_uint4(f2tf(va[i].x), f2tf(va[i].y), f2tf(va[i].z), f2tf(va[i].w));
                *(uint4*)&As[nxt][ar[i]][ac[i]] = u;
            }
            uint4 u = make_uint4(f2tf(vb.x), f2tf(vb.y), f2tf(vb.z), f2tf(vb.w));
            *(uint4*)&Bs[nxt][brow][bc] = u;
            __syncthreads();
        }
    }

    // epilogue
#pragma unroll
    for (int mt = 0; mt < 2; mt++) {
        int r0 = bm + wm * 32 + mt * 16 + gid;
        int r1 = r0 + 8;
#pragma unroll
        for (int nt = 0; nt < 4; nt++) {
            int col0 = bn + wn * 32 + nt * 8 + tig * 2;
            int col1 = col0 + 1;
            float v0 = acc[mt][nt][0] * alpha;
            float v1 = acc[mt][nt][1] * alpha;
            float v2 = acc[mt][nt][2] * alpha;
            float v3 = acc[mt][nt][3] * alpha;
            if (col0 < N) {
                if (Res) { v0 += Res[(size_t)r0 * N + col0]; v2 += Res[(size_t)r1 * N + col0]; }
                C[(size_t)r0 * N + col0] = v0;
                C[(size_t)r1 * N + col0] = v2;
            }
            if (col1 < N) {
                if (Res) { v1 += Res[(size_t)r0 * N + col1]; v3 += Res[(size_t)r1 * N + col1]; }
                C[(size_t)r0 * N + col1] = v1;
                C[(size_t)r1 * N + col1] = v3;
            }
        }
    }
}

// ---------------- Windowed attention (valid rows) ----------------
// kv buffer layout: [(b*TP+t)][256] = {K(2 groups x 64), V(2 groups x 64)}
__global__ __launch_bounds__(256) void win_attn(
    const float* __restrict__ qb, const float* __restrict__ kv,
    const float* __restrict__ qrel, const int* __restrict__ alen,
    float* __restrict__ ob)
{
    extern __shared__ float sm[];
    float* Qs = sm;                 // 64*65
    float* Ks = Qs + 64 * 65;       // 192*65
    float* Vs = Ks + 192 * 65;      // 192*65
    float* S  = Vs + 192 * 65;      // 64*193

    int c = blockIdx.x + 2;
    int h = blockIdx.y;
    int b = blockIdx.z;
    int cs = c * 64;
    int lim = alen[b] + LCW;
    if (cs >= lim) return;
    int tid = threadIdx.x;
    int g = h >> 2;

    const float* qbase = qb + ((size_t)(b * TP + cs)) * DD + h * 64;
#pragma unroll
    for (int i = 0; i < 4; i++) {
        int e = tid + i * 256;
        int row = e >> 4, dq = (e & 15) * 4;
        float4 v = *(const float4*)(qbase + (size_t)row * DD + dq);
        Qs[row * 65 + dq + 0] = v.x; Qs[row * 65 + dq + 1] = v.y;
        Qs[row * 65 + dq + 2] = v.z; Qs[row * 65 + dq + 3] = v.w;
    }
    const float* kbase = kv + ((size_t)(b * TP + cs - 128)) * 256 + g * 64;
    const float* vbase = kbase + 128;
#pragma unroll
    for (int i = 0; i < 12; i++) {
        int e = tid + i * 256;
        int row = e >> 4, dq = (e & 15) * 4;
        float4 kk = *(const float4*)(kbase + (size_t)row * 256 + dq);
        Ks[row * 65 + dq + 0] = kk.x; Ks[row * 65 + dq + 1] = kk.y;
        Ks[row * 65 + dq + 2] = kk.z; Ks[row * 65 + dq + 3] = kk.w;
        float4 vv = *(const float4*)(vbase + (size_t)row * 256 + dq);
        Vs[row * 65 + dq + 0] = vv.x; Vs[row * 65 + dq + 1] = vv.y;
        Vs[row * 65 + dq + 2] = vv.z; Vs[row * 65 + dq + 3] = vv.w;
    }
    __syncthreads();

    int tx = tid & 15, ty = tid >> 4;
#pragma unroll
    for (int rr = 0; rr < 4; rr++) {
        int r = rr * 16 + ty;
        size_t qr = ((size_t)(b * TP + cs + r) * HH + h) * 383;
#pragma unroll
        for (int jj = 0; jj < 12; jj++) {
            int j = jj * 16 + tx;
            float acc = 0.f;
#pragma unroll
            for (int d = 0; d < 64; d++) acc += Qs[r * 65 + d] * Ks[j * 65 + d];
            int kk = cs - 128 + j;
            float s = (kk < lim) ? (acc + __ldg(&qrel[qr + 319 + r - j])) : NEGINF;
            S[r * 193 + j] = s;
        }
    }
    __syncthreads();

    int lane = tid & 31, wid = tid >> 5;
#pragma unroll
    for (int rw = 0; rw < 8; rw++) {
        int r = rw * 8 + wid;
        float sv[6];
        float m = NEGINF;
#pragma unroll
        for (int t = 0; t < 6; t++) { sv[t] = S[r * 193 + lane + t * 32]; m = fmaxf(m, sv[t]); }
#pragma unroll
        for (int o = 16; o > 0; o >>= 1) m = fmaxf(m, __shfl_xor_sync(0xffffffffu, m, o));
        float ss = 0.f;
#pragma unroll
        for (int t = 0; t < 6; t++) { sv[t] = expf(sv[t] - m); ss += sv[t]; }
#pragma unroll
        for (int o = 16; o > 0; o >>= 1) ss += __shfl_xor_sync(0xffffffffu, ss, o);
        float inv = 1.f / ss;
#pragma unroll
        for (int t = 0; t < 6; t++) S[r * 193 + lane + t * 32] = sv[t] * inv;
    }
    __syncthreads();

#pragma unroll
    for (int rr = 0; rr < 4; rr++) {
        int r = rr * 16 + ty;
        int q = cs + r;
        int d0 = tx * 4;
        float a0 = 0.f, a1 = 0.f, a2 = 0.f, a3 = 0.f;
#pragma unroll 4
        for (int j = 0; j < 192; j++) {
            float p = S[r * 193 + j];
            a0 += p * Vs[j * 65 + d0 + 0];
            a1 += p * Vs[j * 65 + d0 + 1];
            a2 += p * Vs[j * 65 + d0 + 2];
            a3 += p * Vs[j * 65 + d0 + 3];
        }
        if (q < lim) {
            float* op = ob + ((size_t)(b * TT + q - 128)) * DD + h * 64 + d0;
            op[0] = a0; op[1] = a1; op[2] = a2; op[3] = a3;
        }
    }
}

// ---------------- Dense attention (invalid rows: full 1152-key softmax) ----------------
__global__ __launch_bounds__(128) void dense_attn(
    const float* __restrict__ qb, const float* __restrict__ kv,
    const float* __restrict__ qrel, const int* __restrict__ alen,
    float* __restrict__ ob)
{
    __shared__ float Kp[128 * 65];
    __shared__ float sc[TP];
    __shared__ float qv[64];
    __shared__ float red[128];
    int q = 128 + blockIdx.x;
    int h = blockIdx.y, b = blockIdx.z;
    int lim = alen[b] + 128;
    if (q < lim) return;
    int tid = threadIdx.x;
    int g = h >> 2;
    if (tid < 64) qv[tid] = qb[((size_t)(b * TP + q)) * DD + h * 64 + tid];
    size_t qr = ((size_t)(b * TP + q) * HH + h) * 383;

    for (int pg = 0; pg < 9; pg++) {
#pragma unroll
        for (int i = 0; i < 16; i++) {
            int e = tid + i * 128;
            int row = e >> 4, dq = (e & 15) * 4;
            float4 v = *(const float4*)(kv + ((size_t)(b * TP + pg * 128 + row)) * 256 + g * 64 + dq);
            Kp[row * 65 + dq + 0] = v.x; Kp[row * 65 + dq + 1] = v.y;
            Kp[row * 65 + dq + 2] = v.z; Kp[row * 65 + dq + 3] = v.w;
        }
        __syncthreads();
        float acc = 0.f;
#pragma unroll
        for (int d = 0; d < 64; d++) acc += qv[d] * Kp[tid * 65 + d];
        int k = pg * 128 + tid;
        int dist = q - k;
        dist = max(-191, min(191, dist));
        sc[k] = acc + __ldg(&qrel[qr + 191 + dist]);
        __syncthreads();
    }
    float lm = NEGINF;
#pragma unroll
    for (int p = 0; p < 9; p++) lm = fmaxf(lm, sc[tid + p * 128]);
    red[tid] = lm; __syncthreads();
    for (int s = 64; s > 0; s >>= 1) { if (tid < s) red[tid] = fmaxf(red[tid], red[tid + s]); __syncthreads(); }
    float m = red[0];
    __syncthreads();
    float ls = 0.f;
#pragma unroll
    for (int p = 0; p < 9; p++) { float e = expf(sc[tid + p * 128] - m); sc[tid + p * 128] = e; ls += e; }
    red[tid] = ls; __syncthreads();
    for (int s = 64; s > 0; s >>= 1) { if (tid < s) red[tid] += red[tid + s]; __syncthreads(); }
    float inv = 1.f / red[0];
    __syncthreads();
    int d = tid & 63, half = tid >> 6;
    float acc = 0.f;
    for (int pg = 0; pg < 9; pg++) {
#pragma unroll
        for (int i = 0; i < 16; i++) {
            int e = tid + i * 128;
            int row = e >> 4, dq = (e & 15) * 4;
            float4 v = *(const float4*)(kv + ((size_t)(b * TP + pg * 128 + row)) * 256 + 128 + g * 64 + dq);
            Kp[row * 65 + dq + 0] = v.x; Kp[row * 65 + dq + 1] = v.y;
            Kp[row * 65 + dq + 2] = v.z; Kp[row * 65 + dq + 3] = v.w;
        }
        __syncthreads();
        int jb = half * 64;
#pragma unroll 8
        for (int jj = 0; jj < 64; jj++)
            acc += sc[pg * 128 + jb + jj] * Kp[(jb + jj) * 65 + d];
        __syncthreads();
    }
    red[tid] = acc; __syncthreads();
    if (tid < 64) {
        float o = (red[tid] + red[tid + 64]) * inv;
        ob[((size_t)(b * TT + q - 128)) * DD + h * 64 + tid] = o;
    }
}

// ---------------- GLU / SwiGLU ----------------
__global__ void glu_kernel(const float* __restrict__ h, float* __restrict__ o,
                           int rows, int half4, int mode)
{
    int i = blockIdx.x * blockDim.x + threadIdx.x;
    if (i >= rows * half4) return;
    int row = i / half4, cc = i - row * half4;
    const float4* hp = (const float4*)h;
    float4 a = hp[(size_t)row * (2 * half4) + cc];
    float4 g = hp[(size_t)row * (2 * half4) + half4 + cc];
    float4 r;
    if (mode == 0) {
        r.x = a.x / (1.f + expf(-g.x));
        r.y = a.y / (1.f + expf(-g.y));
        r.z = a.z / (1.f + expf(-g.z));
        r.w = a.w / (1.f + expf(-g.w));
    } else {
        r.x = a.x / (1.f + expf(-a.x)) * g.x;
        r.y = a.y / (1.f + expf(-a.y)) * g.y;
        r.z = a.z / (1.f + expf(-a.z)) * g.z;
        r.w = a.w / (1.f + expf(-a.w)) * g.w;
    }
    ((float4*)o)[(size_t)row * half4 + cc] = r;
}

// ---------------- depthwise conv (k=9, pad 4) + SiLU ----------------
__global__ __launch_bounds__(128) void dwconv_silu(
    const float* __restrict__ in, const float* __restrict__ dw, float* __restrict__ out)
{
    int t = blockIdx.x, b = blockIdx.y;
    int d0 = threadIdx.x * 4;
    float w[9][4];
#pragma unroll
    for (int c = 0; c < 4; c++)
#pragma unroll
        for (int j = 0; j < 9; j++)
            w[j][c] = __ldg(&dw[(d0 + c) * 9 + j]);
    float4 acc = make_float4(0.f, 0.f, 0.f, 0.f);
#pragma unroll
    for (int j = 0; j < 9; j++) {
        int tt = t + j - 4;
        if (tt >= 0 && tt < TT) {
            float4 v = *(const float4*)(in + ((size_t)(b * TT + tt)) * DD + d0);
            acc.x += v.x * w[j][0];
            acc.y += v.y * w[j][1];
            acc.z += v.z * w[j][2];
            acc.w += v.w * w[j][3];
        }
    }
    acc.x = acc.x / (1.f + expf(-acc.x));
    acc.y = acc.y / (1.f + expf(-acc.y));
    acc.z = acc.z / (1.f + expf(-acc.z));
    acc.w = acc.w / (1.f + expf(-acc.w));
    *(float4*)(out + ((size_t)(b * TT + t)) * DD + d0) = acc;
}

// ---------------- orchestration ----------------
extern "C" void kernel_launch(void* const* d_in, const int* in_sizes, int n_in,
                              void* d_out, int out_size)
{
    const float* x_in  = (const float*)d_in[0];
    const int*   alen  = (const int*)d_in[1];
    const float* ln1_w = (const float*)d_in[2];
    const float* ln1_b = (const float*)d_in[3];
    const float* wq    = (const float*)d_in[4];
    const float* wk    = (const float*)d_in[5];
    const float* wv    = (const float*)d_in[6];
    const float* wo    = (const float*)d_in[7];
    const float* rel   = (const float*)d_in[8];
    const float* ln2_w = (const float*)d_in[9];
    const float* ln2_b = (const float*)d_in[10];
    const float* pw1   = (const float*)d_in[11];
    const float* dw    = (const float*)d_in[12];
    const float* pw2   = (const float*)d_in[13];
    const float* ln3_w = (const float*)d_in[14];
    const float* ln3_b = (const float*)d_in[15];
    const float* w1    = (const float*)d_in[16];
    const float* w2    = (const float*)d_in[17];

    float* scr = nullptr;
    cudaGetSymbolAddress((void**)&scr, g_scr);
    float* xpad  = scr + OFF_XPAD;
    float* xbuf  = scr + OFF_XBUF;
    float* ybuf  = scr + OFF_YBUF;
    float* qbuf  = scr + OFF_QBUF;
    float* kvbuf = scr + OFF_KVBUF;
    float* qrlb  = scr + OFF_QREL;
    float* obuf  = scr + OFF_OBUF;
    float* hbuf  = scr + OFF_HBUF;
    float* gbuf  = scr + OFF_GBUF;
    float* kvw   = scr + OFF_KVW;

    const int WIN_SMEM = (64 * 65 + 192 * 65 + 192 * 65 + 64 * 193) * 4; // 165888
    cudaFuncSetAttribute(win_attn, cudaFuncAttributeMaxDynamicSharedMemorySize, WIN_SMEM);

    zero_pad_kernel<<<(BB * LCW * DD + 255) / 256, 256>>>(xpad);
    pack_kv<<<(4 * 256 * 512 + 255) / 256, 256>>>(wk, wv, kvw);

    for (int l = 0; l < 4; l++) {
        const float* src = (l == 0) ? x_in : xbuf;
        // LN1 -> ybuf (residual base) + xpad (padded input for projections)
        ln_kernel<<<4096, 128>>>(src, ln1_w + l * 512, ln1_b + l * 512, ybuf, xpad);
        // Q (scaled) and packed KV projections over padded rows
        gemm_tc<<<dim3(8, 36), 256>>>(xpad, wq + (size_t)l * 512 * 512, qbuf, nullptr, 4608, 512, 512, 0.125f);
        gemm_tc<<<dim3(4, 36), 256>>>(xpad, kvw + (size_t)l * 256 * 512, kvbuf, nullptr, 4608, 256, 512, 1.f);
        // relative-position bias table: qrel = Q @ rel^T  (A = qbuf viewed as [36864, 64])
        gemm_tc<<<dim3(6, 288), 256>>>(qbuf, rel + (size_t)l * 383 * 64, qrlb, nullptr, 36864, 383, 64, 1.f);
        // attention
        win_attn<<<dim3(16, 8, 4), 256, WIN_SMEM>>>(qbuf, kvbuf, qrlb, alen, obuf);
        dense_attn<<<dim3(1024, 8, 4), 128>>>(qbuf, kvbuf, qrlb, alen, obuf);
        // O projection + residual
        gemm_tc<<<dim3(8, 32), 256>>>(obuf, wo + (size_t)l * 512 * 512, xbuf, ybuf, 4096, 512, 512, 1.f);
        // conv module
        ln_kernel<<<4096, 128>>>(xbuf, ln2_w + l * 512, ln2_b + l * 512, ybuf, nullptr);
        gemm_tc<<<dim3(16, 32), 256>>>(ybuf, pw1 + (size_t)l * 1024 * 512, hbuf, nullptr, 4096, 1024, 512, 1.f);
        glu_kernel<<<(4096 * 128 + 255) / 256, 256>>>(hbuf, gbuf, 4096, 128, 0);
        dwconv_silu<<<dim3(1024, 4), 128>>>(gbuf, dw + (size_t)l * 512 * 9, hbuf);
        gemm_tc<<<dim3(8, 32), 256>>>(hbuf, pw2 + (size_t)l * 512 * 512, xbuf, ybuf, 4096, 512, 512, 1.f);
        // FFN
        ln_kernel<<<4096, 128>>>(xbuf, ln3_w + l * 512, ln3_b + l * 512, ybuf, nullptr);
        gemm_tc<<<dim3(32, 32), 256>>>(ybuf, w1 + (size_t)l * 2048 * 512, hbuf, nullptr, 4096, 2048, 512, 1.f);
        glu_kernel<<<(4096 * 256 + 255) / 256, 256>>>(hbuf, gbuf, 4096, 256, 1);
        float* dst = (l == 3) ? (float*)d_out : xbuf;
        gemm_tc<<<dim3(8, 32), 256>>>(gbuf, w2 + (size_t)l * 512 * 1024, dst, ybuf, 4096, 512, 1024, 1.f);
    }
}

// round 4
// speedup vs baseline: 2.3783x; 1.7677x over previous
#include <cuda_runtime.h>
#include <math.h>

#define TT 1024
#define BB 4
#define DD 512
#define HH 8
#define TP 1152
#define LCW 128
#define NEGINF (__int_as_float(0xff800000))

// ---------------- scratch (static device memory) ----------------
#define OFF_XPAD  0UL          // 4*1152*512  = 2359296
#define OFF_XBUF  2359296UL    // 2097152
#define OFF_YBUF  4456448UL    // 2097152
#define OFF_QBUF  6553600UL    // 4608*512    = 2359296
#define OFF_KVBUF 8912896UL    // 4608*256    = 1179648
#define OFF_QREL  10092544UL   // 36864*383   = 14118912
#define OFF_OBUF  24211456UL   // 2097152
#define OFF_HBUF  26308608UL   // 8388608
#define OFF_GBUF  34697216UL   // 4194304
#define OFF_KVW   38891520UL   // 4*256*512   = 524288
#define SCR_TOTAL 39415808UL

__device__ float g_scr[SCR_TOTAL];

// ---------------- cp.async helpers ----------------
__device__ __forceinline__ void cpa16(void* smem, const void* g) {
    unsigned s = (unsigned)__cvta_generic_to_shared(smem);
    asm volatile("cp.async.ca.shared.global [%0], [%1], 16;" :: "r"(s), "l"(g));
}
__device__ __forceinline__ void cpa16p(void* smem, const void* g, bool pred) {
    unsigned s = (unsigned)__cvta_generic_to_shared(smem);
    int sz = pred ? 16 : 0;
    asm volatile("cp.async.ca.shared.global [%0], [%1], 16, %2;" :: "r"(s), "l"(g), "r"(sz));
}
__device__ __forceinline__ void cp_commit() {
    asm volatile("cp.async.commit_group;");
}
template <int N>
__device__ __forceinline__ void cp_wait() {
    asm volatile("cp.async.wait_group %0;" :: "n"(N));
}

// ---------------- zero the left-context pad rows of xpad ----------------
__global__ void zero_pad_kernel(float* __restrict__ xpad) {
    int i = blockIdx.x * 256 + threadIdx.x;
    if (i < BB * LCW * DD) {
        int b = i / (LCW * DD);
        int rem = i - b * (LCW * DD);
        xpad[(size_t)b * TP * DD + rem] = 0.f;
    }
}

// ---------------- pack K/V weights: kvw[l][256][512] ----------------
__global__ void pack_kv(const float* __restrict__ wk, const float* __restrict__ wv,
                        float* __restrict__ kvw)
{
    int i = blockIdx.x * 256 + threadIdx.x;
    if (i >= 4 * 256 * 512) return;
    int l = i / (256 * 512);
    int r = (i / 512) % 256;
    int c = i % 512;
    float v = (r < 128) ? wk[(size_t)l * 128 * 512 + r * 512 + c]
                        : wv[(size_t)l * 128 * 512 + (r - 128) * 512 + c];
    kvw[i] = v;
}

// ---------------- LayerNorm ----------------
__global__ __launch_bounds__(128) void ln_kernel(
    const float* __restrict__ x, const float* __restrict__ w,
    const float* __restrict__ bvec, float* __restrict__ out,
    float* __restrict__ outpad)
{
    __shared__ float red[8];
    int r = blockIdx.x;
    int tid = threadIdx.x;
    const float* xr = x + (size_t)r * DD;
    float4 v = *(const float4*)(xr + tid * 4);
    float s  = v.x + v.y + v.z + v.w;
    float sq = v.x * v.x + v.y * v.y + v.z * v.z + v.w * v.w;
#pragma unroll
    for (int o = 16; o > 0; o >>= 1) {
        s  += __shfl_xor_sync(0xffffffffu, s, o);
        sq += __shfl_xor_sync(0xffffffffu, sq, o);
    }
    int warp = tid >> 5;
    if ((tid & 31) == 0) { red[warp] = s; red[4 + warp] = sq; }
    __syncthreads();
    float ts = red[0] + red[1] + red[2] + red[3];
    float tq = red[4] + red[5] + red[6] + red[7];
    float mean = ts * (1.f / DD);
    float var  = tq * (1.f / DD) - mean * mean;
    float inv  = rsqrtf(var + 1e-4f);
    float4 wv = *(const float4*)(w + tid * 4);
    float4 bv = *(const float4*)(bvec + tid * 4);
    float4 o;
    o.x = (v.x - mean) * inv * wv.x + bv.x;
    o.y = (v.y - mean) * inv * wv.y + bv.y;
    o.z = (v.z - mean) * inv * wv.z + bv.z;
    o.w = (v.w - mean) * inv * wv.w + bv.w;
    *(float4*)(out + (size_t)r * DD + tid * 4) = o;
    if (outpad) {
        int b = r >> 10, t = r & 1023;
        *(float4*)(outpad + ((size_t)(b * TP + LCW + t)) * DD + tid * 4) = o;
    }
}

// ---------------- TF32 tensor-core GEMM, 3-stage cp.async ----------------
__device__ __forceinline__ unsigned f2tf(float x) {
    unsigned r;
    asm("cvt.rna.tf32.f32 %0, %1;" : "=r"(r) : "f"(x));
    return r;
}

__device__ __forceinline__ void mma_tf32(float* c, const unsigned* a, const unsigned* b) {
    asm volatile(
        "mma.sync.aligned.m16n8k8.row.col.f32.tf32.tf32.f32 "
        "{%0,%1,%2,%3}, {%4,%5,%6,%7}, {%8,%9}, {%0,%1,%2,%3};"
        : "+f"(c[0]), "+f"(c[1]), "+f"(c[2]), "+f"(c[3])
        : "r"(a[0]), "r"(a[1]), "r"(a[2]), "r"(a[3]), "r"(b[0]), "r"(b[1]));
}

__global__ __launch_bounds__(256) void gemm_tc(
    const float* __restrict__ A, const float* __restrict__ B,
    float* __restrict__ C, const float* __restrict__ Res,
    int M, int N, int K, float alpha)
{
    __shared__ float As[3][128][20];
    __shared__ float Bs[3][64][20];

    int tid = threadIdx.x;
    int bm = blockIdx.y * 128;
    int bn = blockIdx.x * 64;
    int wid = tid >> 5, lane = tid & 31;
    int wm = wid & 3, wn = wid >> 2;        // 4x2 warp grid, 32x32 warp tile
    int gid = lane >> 2, tig = lane & 3;

    float acc[2][4][4];
#pragma unroll
    for (int i = 0; i < 2; i++)
#pragma unroll
        for (int j = 0; j < 4; j++)
#pragma unroll
            for (int q = 0; q < 4; q++) acc[i][j][q] = 0.f;

    int ar[2], ac[2];
#pragma unroll
    for (int i = 0; i < 2; i++) {
        int idx = tid + i * 256;
        ar[i] = idx >> 2;
        ac[i] = (idx & 3) * 4;
    }
    int brow = tid >> 2;
    int bc   = (tid & 3) * 4;
    bool bpred = (bn + brow < N);

    const float* ap0 = A + (size_t)(bm + ar[0]) * K + ac[0];
    const float* ap1 = A + (size_t)(bm + ar[1]) * K + ac[1];
    const float* bp  = B + (size_t)(bn + brow) * K + bc;

    int nIters = K >> 4;

    // prologue: stages 0, 1
    cpa16(&As[0][ar[0]][ac[0]], ap0);
    cpa16(&As[0][ar[1]][ac[1]], ap1);
    cpa16p(&Bs[0][brow][bc], bp, bpred);
    cp_commit();
    if (nIters > 1) {
        cpa16(&As[1][ar[0]][ac[0]], ap0 + 16);
        cpa16(&As[1][ar[1]][ac[1]], ap1 + 16);
        cpa16p(&Bs[1][brow][bc], bp + 16, bpred);
    }
    cp_commit();

    for (int t = 0; t < nIters; t++) {
        cp_wait<1>();
        __syncthreads();
        if (t + 2 < nIters) {
            int k0 = (t + 2) << 4;
            int st = (t + 2) % 3;
            cpa16(&As[st][ar[0]][ac[0]], ap0 + k0);
            cpa16(&As[st][ar[1]][ac[1]], ap1 + k0);
            cpa16p(&Bs[st][brow][bc], bp + k0, bpred);
        }
        cp_commit();

        int cur = t % 3;
        const float (*Ac)[20] = As[cur];
        const float (*Bc)[20] = Bs[cur];
#pragma unroll
        for (int ks = 0; ks < 2; ks++) {
            int kk = ks * 8;
            unsigned a[2][4], b[4][2];
#pragma unroll
            for (int mt = 0; mt < 2; mt++) {
                int m0 = wm * 32 + mt * 16 + gid;
                a[mt][0] = f2tf(Ac[m0][kk + tig]);
                a[mt][1] = f2tf(Ac[m0 + 8][kk + tig]);
                a[mt][2] = f2tf(Ac[m0][kk + tig + 4]);
                a[mt][3] = f2tf(Ac[m0 + 8][kk + tig + 4]);
            }
#pragma unroll
            for (int nt = 0; nt < 4; nt++) {
                int n0 = wn * 32 + nt * 8 + gid;
                b[nt][0] = f2tf(Bc[n0][kk + tig]);
                b[nt][1] = f2tf(Bc[n0][kk + tig + 4]);
            }
#pragma unroll
            for (int mt = 0; mt < 2; mt++)
#pragma unroll
                for (int nt = 0; nt < 4; nt++)
                    mma_tf32(acc[mt][nt], a[mt], b[nt]);
        }
    }

    // epilogue
#pragma unroll
    for (int mt = 0; mt < 2; mt++) {
        int r0 = bm + wm * 32 + mt * 16 + gid;
        int r1 = r0 + 8;
#pragma unroll
        for (int nt = 0; nt < 4; nt++) {
            int col0 = bn + wn * 32 + nt * 8 + tig * 2;
            int col1 = col0 + 1;
            float v0 = acc[mt][nt][0] * alpha;
            float v1 = acc[mt][nt][1] * alpha;
            float v2 = acc[mt][nt][2] * alpha;
            float v3 = acc[mt][nt][3] * alpha;
            if (col0 < N) {
                if (Res) { v0 += Res[(size_t)r0 * N + col0]; v2 += Res[(size_t)r1 * N + col0]; }
                C[(size_t)r0 * N + col0] = v0;
                C[(size_t)r1 * N + col0] = v2;
            }
            if (col1 < N) {
                if (Res) { v1 += Res[(size_t)r0 * N + col1]; v3 += Res[(size_t)r1 * N + col1]; }
                C[(size_t)r0 * N + col1] = v1;
                C[(size_t)r1 * N + col1] = v3;
            }
        }
    }
}

// ---------------- Windowed attention (valid rows) ----------------
__global__ __launch_bounds__(256) void win_attn(
    const float* __restrict__ qb, const float* __restrict__ kv,
    const float* __restrict__ qrel, const int* __restrict__ alen,
    float* __restrict__ ob)
{
    extern __shared__ float sm[];
    float* Qs = sm;                 // 64*65
    float* Ks = Qs + 64 * 65;       // 192*65
    float* Vs = Ks + 192 * 65;      // 192*65
    float* S  = Vs + 192 * 65;      // 64*193

    int c = blockIdx.x + 2;
    int h = blockIdx.y;
    int b = blockIdx.z;
    int cs = c * 64;
    int lim = alen[b] + LCW;
    if (cs >= lim) return;
    int tid = threadIdx.x;
    int g = h >> 2;

    const float* qbase = qb + ((size_t)(b * TP + cs)) * DD + h * 64;
#pragma unroll
    for (int i = 0; i < 4; i++) {
        int e = tid + i * 256;
        int row = e >> 4, dq = (e & 15) * 4;
        float4 v = *(const float4*)(qbase + (size_t)row * DD + dq);
        Qs[row * 65 + dq + 0] = v.x; Qs[row * 65 + dq + 1] = v.y;
        Qs[row * 65 + dq + 2] = v.z; Qs[row * 65 + dq + 3] = v.w;
    }
    const float* kbase = kv + ((size_t)(b * TP + cs - 128)) * 256 + g * 64;
    const float* vbase = kbase + 128;
#pragma unroll
    for (int i = 0; i < 12; i++) {
        int e = tid + i * 256;
        int row = e >> 4, dq = (e & 15) * 4;
        float4 kk = *(const float4*)(kbase + (size_t)row * 256 + dq);
        Ks[row * 65 + dq + 0] = kk.x; Ks[row * 65 + dq + 1] = kk.y;
        Ks[row * 65 + dq + 2] = kk.z; Ks[row * 65 + dq + 3] = kk.w;
        float4 vv = *(const float4*)(vbase + (size_t)row * 256 + dq);
        Vs[row * 65 + dq + 0] = vv.x; Vs[row * 65 + dq + 1] = vv.y;
        Vs[row * 65 + dq + 2] = vv.z; Vs[row * 65 + dq + 3] = vv.w;
    }
    __syncthreads();

    int tx = tid & 15, ty = tid >> 4;
#pragma unroll
    for (int rr = 0; rr < 4; rr++) {
        int r = rr * 16 + ty;
        size_t qr = ((size_t)(b * TP + cs + r) * HH + h) * 383;
#pragma unroll
        for (int jj = 0; jj < 12; jj++) {
            int j = jj * 16 + tx;
            float acc = 0.f;
#pragma unroll
            for (int d = 0; d < 64; d++) acc += Qs[r * 65 + d] * Ks[j * 65 + d];
            int kk = cs - 128 + j;
            float s = (kk < lim) ? (acc + __ldg(&qrel[qr + 319 + r - j])) : NEGINF;
            S[r * 193 + j] = s;
        }
    }
    __syncthreads();

    int lane = tid & 31, wid = tid >> 5;
#pragma unroll
    for (int rw = 0; rw < 8; rw++) {
        int r = rw * 8 + wid;
        float sv[6];
        float m = NEGINF;
#pragma unroll
        for (int t = 0; t < 6; t++) { sv[t] = S[r * 193 + lane + t * 32]; m = fmaxf(m, sv[t]); }
#pragma unroll
        for (int o = 16; o > 0; o >>= 1) m = fmaxf(m, __shfl_xor_sync(0xffffffffu, m, o));
        float ss = 0.f;
#pragma unroll
        for (int t = 0; t < 6; t++) { sv[t] = expf(sv[t] - m); ss += sv[t]; }
#pragma unroll
        for (int o = 16; o > 0; o >>= 1) ss += __shfl_xor_sync(0xffffffffu, ss, o);
        float inv = 1.f / ss;
#pragma unroll
        for (int t = 0; t < 6; t++) S[r * 193 + lane + t * 32] = sv[t] * inv;
    }
    __syncthreads();

#pragma unroll
    for (int rr = 0; rr < 4; rr++) {
        int r = rr * 16 + ty;
        int q = cs + r;
        int d0 = tx * 4;
        float a0 = 0.f, a1 = 0.f, a2 = 0.f, a3 = 0.f;
#pragma unroll 4
        for (int j = 0; j < 192; j++) {
            float p = S[r * 193 + j];
            a0 += p * Vs[j * 65 + d0 + 0];
            a1 += p * Vs[j * 65 + d0 + 1];
            a2 += p * Vs[j * 65 + d0 + 2];
            a3 += p * Vs[j * 65 + d0 + 3];
        }
        if (q < lim) {
            float* op = ob + ((size_t)(b * TT + q - 128)) * DD + h * 64 + d0;
            op[0] = a0; op[1] = a1; op[2] = a2; op[3] = a3;
        }
    }
}

// ---------------- Dense flash attention (invalid rows, chunked) ----------------
// Block per (chunk c=2..17, head, batch). Handles rows q = cs..cs+63 with
// q >= lim (full unmasked 1152-key softmax). Online (flash) softmax over
// 9 pages of 128 keys.
__global__ __launch_bounds__(256) void dense_flash(
    const float* __restrict__ qb, const float* __restrict__ kv,
    const float* __restrict__ qrel, const int* __restrict__ alen,
    float* __restrict__ ob)
{
    extern __shared__ float sm[];
    float* Qs = sm;                  // 64*65   = 4160
    float* Ks = Qs + 64 * 65;        // 128*65  = 8320
    float* Vs = Ks + 128 * 65;       // 8320
    float* S  = Vs + 128 * 65;       // 64*132  = 8448
    float* rowm  = S + 64 * 132;     // 64
    float* rowsum = rowm + 64;       // 64
    float* rowscale = rowsum + 64;   // 64

    int c = blockIdx.x + 2;
    int h = blockIdx.y;
    int b = blockIdx.z;
    int cs = c * 64;
    int lim = alen[b] + LCW;
    if (cs + 64 <= lim) return;      // no invalid rows in this chunk
    int tid = threadIdx.x;
    int g = h >> 2;
    int tx = tid & 15, ty = tid >> 4;
    int lane = tid & 31, wd = tid >> 5;

    // load Q chunk
    const float* qbase = qb + ((size_t)(b * TP + cs)) * DD + h * 64;
#pragma unroll
    for (int i = 0; i < 4; i++) {
        int e = tid + i * 256;
        int row = e >> 4, dq = (e & 15) * 4;
        float4 v = *(const float4*)(qbase + (size_t)row * DD + dq);
        Qs[row * 65 + dq + 0] = v.x; Qs[row * 65 + dq + 1] = v.y;
        Qs[row * 65 + dq + 2] = v.z; Qs[row * 65 + dq + 3] = v.w;
    }
    if (tid < 64) { rowm[tid] = NEGINF; rowsum[tid] = 0.f; }

    float acc[4][4];
#pragma unroll
    for (int rr = 0; rr < 4; rr++)
#pragma unroll
        for (int q4 = 0; q4 < 4; q4++) acc[rr][q4] = 0.f;

    __syncthreads();

    for (int pg = 0; pg < 9; pg++) {
        // load K,V page (128 keys x 64 dims each)
        const float* kp = kv + ((size_t)(b * TP + pg * 128)) * 256 + g * 64;
#pragma unroll
        for (int i = 0; i < 8; i++) {
            int e = tid + i * 256;
            int row = e >> 4, dq = (e & 15) * 4;
            float4 kk = *(const float4*)(kp + (size_t)row * 256 + dq);
            Ks[row * 65 + dq + 0] = kk.x; Ks[row * 65 + dq + 1] = kk.y;
            Ks[row * 65 + dq + 2] = kk.z; Ks[row * 65 + dq + 3] = kk.w;
            float4 vv = *(const float4*)(kp + (size_t)row * 256 + 128 + dq);
            Vs[row * 65 + dq + 0] = vv.x; Vs[row * 65 + dq + 1] = vv.y;
            Vs[row * 65 + dq + 2] = vv.z; Vs[row * 65 + dq + 3] = vv.w;
        }
        __syncthreads();

        // scores: 4 rows x 8 keys per thread
        float accS[4][8];
#pragma unroll
        for (int rr = 0; rr < 4; rr++)
#pragma unroll
            for (int jj = 0; jj < 8; jj++) accS[rr][jj] = 0.f;
#pragma unroll 8
        for (int d = 0; d < 64; d++) {
            float kvv[8];
#pragma unroll
            for (int jj = 0; jj < 8; jj++) kvv[jj] = Ks[(jj * 16 + tx) * 65 + d];
#pragma unroll
            for (int rr = 0; rr < 4; rr++) {
                float qv = Qs[(rr * 16 + ty) * 65 + d];
#pragma unroll
                for (int jj = 0; jj < 8; jj++) accS[rr][jj] += qv * kvv[jj];
            }
        }
#pragma unroll
        for (int rr = 0; rr < 4; rr++) {
            int r = rr * 16 + ty;
            int q = cs + r;
            size_t qr = ((size_t)(b * TP + q) * HH + h) * 383;
#pragma unroll
            for (int jj = 0; jj < 8; jj++) {
                int j = jj * 16 + tx;
                int k = pg * 128 + j;
                int dist = q - k;
                dist = max(-191, min(191, dist));
                S[r * 132 + j] = accS[rr][jj] + __ldg(&qrel[qr + 191 + dist]);
            }
        }
        __syncthreads();

        // online softmax update: warp wd handles rows 8*wd..8*wd+7
#pragma unroll
        for (int rw = 0; rw < 8; rw++) {
            int r = wd * 8 + rw;
            float v0 = S[r * 132 + lane];
            float v1 = S[r * 132 + lane + 32];
            float v2 = S[r * 132 + lane + 64];
            float v3 = S[r * 132 + lane + 96];
            float mn = fmaxf(fmaxf(v0, v1), fmaxf(v2, v3));
#pragma unroll
            for (int o = 16; o > 0; o >>= 1) mn = fmaxf(mn, __shfl_xor_sync(0xffffffffu, mn, o));
            float mo = rowm[r];
            float mp = fmaxf(mo, mn);
            float p0 = expf(v0 - mp), p1 = expf(v1 - mp), p2 = expf(v2 - mp), p3 = expf(v3 - mp);
            S[r * 132 + lane] = p0; S[r * 132 + lane + 32] = p1;
            S[r * 132 + lane + 64] = p2; S[r * 132 + lane + 96] = p3;
            float ss = p0 + p1 + p2 + p3;
#pragma unroll
            for (int o = 16; o > 0; o >>= 1) ss += __shfl_xor_sync(0xffffffffu, ss, o);
            if (lane == 0) {
                float scale = expf(mo - mp);
                rowm[r] = mp;
                rowscale[r] = scale;
                rowsum[r] = rowsum[r] * scale + ss;
            }
        }
        __syncthreads();

        // PV accumulate with rescale
        int d0 = tx * 4;
#pragma unroll
        for (int rr = 0; rr < 4; rr++) {
            int r = rr * 16 + ty;
            float sc = rowscale[r];
#pragma unroll
            for (int q4 = 0; q4 < 4; q4++) acc[rr][q4] *= sc;
        }
#pragma unroll 4
        for (int j = 0; j < 128; j++) {
            float w0 = Vs[j * 65 + d0 + 0];
            float w1 = Vs[j * 65 + d0 + 1];
            float w2 = Vs[j * 65 + d0 + 2];
            float w3 = Vs[j * 65 + d0 + 3];
#pragma unroll
            for (int rr = 0; rr < 4; rr++) {
                float p = S[(rr * 16 + ty) * 132 + j];
                acc[rr][0] += p * w0; acc[rr][1] += p * w1;
                acc[rr][2] += p * w2; acc[rr][3] += p * w3;
            }
        }
        __syncthreads();
    }

    // store invalid rows only (valid rows written by win_attn)
    int d0 = tx * 4;
#pragma unroll
    for (int rr = 0; rr < 4; rr++) {
        int r = rr * 16 + ty;
        int q = cs + r;
        if (q >= lim) {
            float inv = 1.f / rowsum[r];
            float* op = ob + ((size_t)(b * TT + q - 128)) * DD + h * 64 + d0;
            op[0] = acc[rr][0] * inv;
            op[1] = acc[rr][1] * inv;
            op[2] = acc[rr][2] * inv;
            op[3] = acc[rr][3] * inv;
        }
    }
}

// ---------------- GLU / SwiGLU ----------------
__global__ void glu_kernel(const float* __restrict__ h, float* __restrict__ o,
                           int rows, int half4, int mode)
{
    int i = blockIdx.x * blockDim.x + threadIdx.x;
    if (i >= rows * half4) return;
    int row = i / half4, cc = i - row * half4;
    const float4* hp = (const float4*)h;
    float4 a = hp[(size_t)row * (2 * half4) + cc];
    float4 g = hp[(size_t)row * (2 * half4) + half4 + cc];
    float4 r;
    if (mode == 0) {
        r.x = a.x / (1.f + expf(-g.x));
        r.y = a.y / (1.f + expf(-g.y));
        r.z = a.z / (1.f + expf(-g.z));
        r.w = a.w / (1.f + expf(-g.w));
    } else {
        r.x = a.x / (1.f + expf(-a.x)) * g.x;
        r.y = a.y / (1.f + expf(-a.y)) * g.y;
        r.z = a.z / (1.f + expf(-a.z)) * g.z;
        r.w = a.w / (1.f + expf(-a.w)) * g.w;
    }
    ((float4*)o)[(size_t)row * half4 + cc] = r;
}

// ---------------- depthwise conv (k=9, pad 4) + SiLU ----------------
__global__ __launch_bounds__(128) void dwconv_silu(
    const float* __restrict__ in, const float* __restrict__ dw, float* __restrict__ out)
{
    int t = blockIdx.x, b = blockIdx.y;
    int d0 = threadIdx.x * 4;
    float w[9][4];
#pragma unroll
    for (int c = 0; c < 4; c++)
#pragma unroll
        for (int j = 0; j < 9; j++)
            w[j][c] = __ldg(&dw[(d0 + c) * 9 + j]);
    float4 acc = make_float4(0.f, 0.f, 0.f, 0.f);
#pragma unroll
    for (int j = 0; j < 9; j++) {
        int tt = t + j - 4;
        if (tt >= 0 && tt < TT) {
            float4 v = *(const float4*)(in + ((size_t)(b * TT + tt)) * DD + d0);
            acc.x += v.x * w[j][0];
            acc.y += v.y * w[j][1];
            acc.z += v.z * w[j][2];
            acc.w += v.w * w[j][3];
        }
    }
    acc.x = acc.x / (1.f + expf(-acc.x));
    acc.y = acc.y / (1.f + expf(-acc.y));
    acc.z = acc.z / (1.f + expf(-acc.z));
    acc.w = acc.w / (1.f + expf(-acc.w));
    *(float4*)(out + ((size_t)(b * TT + t)) * DD + d0) = acc;
}

// ---------------- orchestration ----------------
extern "C" void kernel_launch(void* const* d_in, const int* in_sizes, int n_in,
                              void* d_out, int out_size)
{
    const float* x_in  = (const float*)d_in[0];
    const int*   alen  = (const int*)d_in[1];
    const float* ln1_w = (const float*)d_in[2];
    const float* ln1_b = (const float*)d_in[3];
    const float* wq    = (const float*)d_in[4];
    const float* wk    = (const float*)d_in[5];
    const float* wv    = (const float*)d_in[6];
    const float* wo    = (const float*)d_in[7];
    const float* rel   = (const float*)d_in[8];
    const float* ln2_w = (const float*)d_in[9];
    const float* ln2_b = (const float*)d_in[10];
    const float* pw1   = (const float*)d_in[11];
    const float* dw    = (const float*)d_in[12];
    const float* pw2   = (const float*)d_in[13];
    const float* ln3_w = (const float*)d_in[14];
    const float* ln3_b = (const float*)d_in[15];
    const float* w1    = (const float*)d_in[16];
    const float* w2    = (const float*)d_in[17];

    float* scr = nullptr;
    cudaGetSymbolAddress((void**)&scr, g_scr);
    float* xpad  = scr + OFF_XPAD;
    float* xbuf  = scr + OFF_XBUF;
    float* ybuf  = scr + OFF_YBUF;
    float* qbuf  = scr + OFF_QBUF;
    float* kvbuf = scr + OFF_KVBUF;
    float* qrlb  = scr + OFF_QREL;
    float* obuf  = scr + OFF_OBUF;
    float* hbuf  = scr + OFF_HBUF;
    float* gbuf  = scr + OFF_GBUF;
    float* kvw   = scr + OFF_KVW;

    const int WIN_SMEM = (64 * 65 + 192 * 65 + 192 * 65 + 64 * 193) * 4; // 165888
    const int DF_SMEM  = (64 * 65 + 128 * 65 + 128 * 65 + 64 * 132 + 192) * 4; // 117760
    cudaFuncSetAttribute(win_attn, cudaFuncAttributeMaxDynamicSharedMemorySize, WIN_SMEM);
    cudaFuncSetAttribute(dense_flash, cudaFuncAttributeMaxDynamicSharedMemorySize, DF_SMEM);

    zero_pad_kernel<<<(BB * LCW * DD + 255) / 256, 256>>>(xpad);
    pack_kv<<<(4 * 256 * 512 + 255) / 256, 256>>>(wk, wv, kvw);

    for (int l = 0; l < 4; l++) {
        const float* src = (l == 0) ? x_in : xbuf;
        ln_kernel<<<4096, 128>>>(src, ln1_w + l * 512, ln1_b + l * 512, ybuf, xpad);
        gemm_tc<<<dim3(8, 36), 256>>>(xpad, wq + (size_t)l * 512 * 512, qbuf, nullptr, 4608, 512, 512, 0.125f);
        gemm_tc<<<dim3(4, 36), 256>>>(xpad, kvw + (size_t)l * 256 * 512, kvbuf, nullptr, 4608, 256, 512, 1.f);
        gemm_tc<<<dim3(6, 288), 256>>>(qbuf, rel + (size_t)l * 383 * 64, qrlb, nullptr, 36864, 383, 64, 1.f);
        win_attn<<<dim3(16, 8, 4), 256, WIN_SMEM>>>(qbuf, kvbuf, qrlb, alen, obuf);
        dense_flash<<<dim3(16, 8, 4), 256, DF_SMEM>>>(qbuf, kvbuf, qrlb, alen, obuf);
        gemm_tc<<<dim3(8, 32), 256>>>(obuf, wo + (size_t)l * 512 * 512, xbuf, ybuf, 4096, 512, 512, 1.f);
        ln_kernel<<<4096, 128>>>(xbuf, ln2_w + l * 512, ln2_b + l * 512, ybuf, nullptr);
        gemm_tc<<<dim3(16, 32), 256>>>(ybuf, pw1 + (size_t)l * 1024 * 512, hbuf, nullptr, 4096, 1024, 512, 1.f);
        glu_kernel<<<(4096 * 128 + 255) / 256, 256>>>(hbuf, gbuf, 4096, 128, 0);
        dwconv_silu<<<dim3(1024, 4), 128>>>(gbuf, dw + (size_t)l * 512 * 9, hbuf);
        gemm_tc<<<dim3(8, 32), 256>>>(hbuf, pw2 + (size_t)l * 512 * 512, xbuf, ybuf, 4096, 512, 512, 1.f);
        ln_kernel<<<4096, 128>>>(xbuf, ln3_w + l * 512, ln3_b + l * 512, ybuf, nullptr);
        gemm_tc<<<dim3(32, 32), 256>>>(ybuf, w1 + (size_t)l * 2048 * 512, hbuf, nullptr, 4096, 2048, 512, 1.f);
        glu_kernel<<<(4096 * 256 + 255) / 256, 256>>>(hbuf, gbuf, 4096, 256, 1);
        float* dst = (l == 3) ? (float*)d_out : xbuf;
        gemm_tc<<<dim3(8, 32), 256>>>(gbuf, w2 + (size_t)l * 512 * 1024, dst, ybuf, 4096, 512, 1024, 1.f);
    }
}

// round 5
// speedup vs baseline: 2.6299x; 1.1058x over previous
#include <cuda_runtime.h>
#include <math.h>

#define TT 1024
#define BB 4
#define DD 512
#define HH 8
#define TP 1152
#define LCW 128
#define NEGINF (__int_as_float(0xff800000))

// ---------------- scratch (static device memory) ----------------
#define OFF_XPAD  0UL          // 4*1152*512  = 2359296
#define OFF_XBUF  2359296UL    // 2097152
#define OFF_YBUF  4456448UL    // 2097152
#define OFF_QBUF  6553600UL    // 4608*512    = 2359296
#define OFF_KVBUF 8912896UL    // 4608*256    = 1179648
#define OFF_QREL  10092544UL   // 36864*383   = 14118912
#define OFF_OBUF  24211456UL   // 2097152
#define OFF_HBUF  26308608UL   // 8388608
#define OFF_GBUF  34697216UL   // 4194304
#define OFF_KVW   38891520UL   // 4*256*512   = 524288
#define OFF_PW1P  39415808UL   // 4*1024*512  = 2097152
#define OFF_W1P   41512960UL   // 4*2048*512  = 4194304
#define SCR_TOTAL 45707264UL

__device__ float g_scr[SCR_TOTAL];

// ---------------- cp.async helpers ----------------
__device__ __forceinline__ void cpa16(void* smem, const void* g) {
    unsigned s = (unsigned)__cvta_generic_to_shared(smem);
    asm volatile("cp.async.ca.shared.global [%0], [%1], 16;" :: "r"(s), "l"(g));
}
__device__ __forceinline__ void cpa16p(void* smem, const void* g, bool pred) {
    unsigned s = (unsigned)__cvta_generic_to_shared(smem);
    int sz = pred ? 16 : 0;
    asm volatile("cp.async.ca.shared.global [%0], [%1], 16, %2;" :: "r"(s), "l"(g), "r"(sz));
}
__device__ __forceinline__ void cp_commit() {
    asm volatile("cp.async.commit_group;");
}
template <int N>
__device__ __forceinline__ void cp_wait() {
    asm volatile("cp.async.wait_group %0;" :: "n"(N));
}
__device__ __forceinline__ void ldm_x4(unsigned& r0, unsigned& r1, unsigned& r2, unsigned& r3,
                                       const void* p) {
    unsigned a = (unsigned)__cvta_generic_to_shared(p);
    asm volatile("ldmatrix.sync.aligned.m8n8.x4.shared.b16 {%0,%1,%2,%3}, [%4];"
                 : "=r"(r0), "=r"(r1), "=r"(r2), "=r"(r3) : "r"(a));
}

// ---------------- zero the left-context pad rows of xpad ----------------
__global__ void zero_pad_kernel(float* __restrict__ xpad) {
    int i = blockIdx.x * 256 + threadIdx.x;
    if (i < BB * LCW * DD) {
        int b = i / (LCW * DD);
        int rem = i - b * (LCW * DD);
        xpad[(size_t)b * TP * DD + rem] = 0.f;
    }
}

// ---------------- pack K/V weights: kvw[l][256][512] ----------------
__global__ void pack_kv(const float* __restrict__ wk, const float* __restrict__ wv,
                        float* __restrict__ kvw)
{
    int i = blockIdx.x * 256 + threadIdx.x;
    if (i >= 4 * 256 * 512) return;
    int l = i / (256 * 512);
    int r = (i / 512) % 256;
    int c = i % 512;
    float v = (r < 128) ? wk[(size_t)l * 128 * 512 + r * 512 + c]
                        : wv[(size_t)l * 128 * 512 + (r - 128) * 512 + c];
    kvw[i] = v;
}

// ---------------- interleave GLU weight halves: out row 2i=a_i, 2i+1=g_i ----------------
__global__ void pack_glu(const float* __restrict__ w, float* __restrict__ wp,
                         int half, int total)
{
    int i = blockIdx.x * 256 + threadIdx.x;
    if (i >= total) return;
    int per = 2 * half * 512;
    int l = i / per;
    int rem = i - l * per;
    int r = rem / 512;
    int c = rem - r * 512;
    int src = (r & 1) ? (half + (r >> 1)) : (r >> 1);
    wp[i] = w[(size_t)l * per + (size_t)src * 512 + c];
}

// ---------------- LayerNorm ----------------
__global__ __launch_bounds__(128) void ln_kernel(
    const float* __restrict__ x, const float* __restrict__ w,
    const float* __restrict__ bvec, float* __restrict__ out,
    float* __restrict__ outpad)
{
    __shared__ float red[8];
    int r = blockIdx.x;
    int tid = threadIdx.x;
    const float* xr = x + (size_t)r * DD;
    float4 v = *(const float4*)(xr + tid * 4);
    float s  = v.x + v.y + v.z + v.w;
    float sq = v.x * v.x + v.y * v.y + v.z * v.z + v.w * v.w;
#pragma unroll
    for (int o = 16; o > 0; o >>= 1) {
        s  += __shfl_xor_sync(0xffffffffu, s, o);
        sq += __shfl_xor_sync(0xffffffffu, sq, o);
    }
    int warp = tid >> 5;
    if ((tid & 31) == 0) { red[warp] = s; red[4 + warp] = sq; }
    __syncthreads();
    float ts = red[0] + red[1] + red[2] + red[3];
    float tq = red[4] + red[5] + red[6] + red[7];
    float mean = ts * (1.f / DD);
    float var  = tq * (1.f / DD) - mean * mean;
    float inv  = rsqrtf(var + 1e-4f);
    float4 wv = *(const float4*)(w + tid * 4);
    float4 bv = *(const float4*)(bvec + tid * 4);
    float4 o;
    o.x = (v.x - mean) * inv * wv.x + bv.x;
    o.y = (v.y - mean) * inv * wv.y + bv.y;
    o.z = (v.z - mean) * inv * wv.z + bv.z;
    o.w = (v.w - mean) * inv * wv.w + bv.w;
    *(float4*)(out + (size_t)r * DD + tid * 4) = o;
    if (outpad) {
        int b = r >> 10, t = r & 1023;
        *(float4*)(outpad + ((size_t)(b * TP + LCW + t)) * DD + tid * 4) = o;
    }
}

// ---------------- TF32 tensor-core GEMM, 3-stage cp.async + ldmatrix ----------------
// mode 0: C = alpha*A@B^T (+Res), N guarded
// mode 1: GLU      out[., n] = h0*sigmoid(h1) on adjacent col pairs (N%64==0)
// mode 2: SwiGLU   out[., n] = silu(h0)*h1
__device__ __forceinline__ void mma_tf32(float* c, const unsigned* a, const unsigned* b) {
    asm volatile(
        "mma.sync.aligned.m16n8k8.row.col.f32.tf32.tf32.f32 "
        "{%0,%1,%2,%3}, {%4,%5,%6,%7}, {%8,%9}, {%0,%1,%2,%3};"
        : "+f"(c[0]), "+f"(c[1]), "+f"(c[2]), "+f"(c[3])
        : "r"(a[0]), "r"(a[1]), "r"(a[2]), "r"(a[3]), "r"(b[0]), "r"(b[1]));
}

__global__ __launch_bounds__(256) void gemm_tc(
    const float* __restrict__ A, const float* __restrict__ B,
    float* __restrict__ C, const float* __restrict__ Res,
    int M, int N, int K, float alpha, int mode)
{
    __shared__ float As[3][128][20];
    __shared__ float Bs[3][64][20];

    int tid = threadIdx.x;
    int bm = blockIdx.y * 128;
    int bn = blockIdx.x * 64;
    int wid = tid >> 5, lane = tid & 31;
    int wm = wid & 3, wn = wid >> 2;        // 4x2 warp grid, 32x32 warp tile
    int gid = lane >> 2, tig = lane & 3;

    float acc[2][4][4];
#pragma unroll
    for (int i = 0; i < 2; i++)
#pragma unroll
        for (int j = 0; j < 4; j++)
#pragma unroll
            for (int q = 0; q < 4; q++) acc[i][j][q] = 0.f;

    int ar[2], ac[2];
#pragma unroll
    for (int i = 0; i < 2; i++) {
        int idx = tid + i * 256;
        ar[i] = idx >> 2;
        ac[i] = (idx & 3) * 4;
    }
    int brow = tid >> 2;
    int bc   = (tid & 3) * 4;
    bool bpred = (bn + brow < N);

    const float* ap0 = A + (size_t)(bm + ar[0]) * K + ac[0];
    const float* ap1 = A + (size_t)(bm + ar[1]) * K + ac[1];
    const float* bp  = B + (size_t)(bn + brow) * K + bc;

    int nIters = K >> 4;

    // ldmatrix lane-derived offsets
    int aRow = lane & 15;                // row within 16-row fragment
    int aCol = (lane < 16) ? 0 : 4;      // k offset within 8-wide k-slice

    // prologue: stages 0, 1
    cpa16(&As[0][ar[0]][ac[0]], ap0);
    cpa16(&As[0][ar[1]][ac[1]], ap1);
    cpa16p(&Bs[0][brow][bc], bp, bpred);
    cp_commit();
    if (nIters > 1) {
        cpa16(&As[1][ar[0]][ac[0]], ap0 + 16);
        cpa16(&As[1][ar[1]][ac[1]], ap1 + 16);
        cpa16p(&Bs[1][brow][bc], bp + 16, bpred);
    }
    cp_commit();

    for (int t = 0; t < nIters; t++) {
        cp_wait<1>();
        __syncthreads();
        if (t + 2 < nIters) {
            int k0 = (t + 2) << 4;
            int st = (t + 2) % 3;
            cpa16(&As[st][ar[0]][ac[0]], ap0 + k0);
            cpa16(&As[st][ar[1]][ac[1]], ap1 + k0);
            cpa16p(&Bs[st][brow][bc], bp + k0, bpred);
        }
        cp_commit();

        int cur = t % 3;
        const float (*Ac)[20] = As[cur];
        const float (*Bc)[20] = Bs[cur];
#pragma unroll
        for (int ks = 0; ks < 2; ks++) {
            int kk = ks * 8;
            unsigned a0f[4], a1f[4], bL[4], bH[4];
            ldm_x4(a0f[0], a0f[1], a0f[2], a0f[3], &Ac[wm * 32 + aRow][kk + aCol]);
            ldm_x4(a1f[0], a1f[1], a1f[2], a1f[3], &Ac[wm * 32 + 16 + aRow][kk + aCol]);
            ldm_x4(bL[0], bL[1], bL[2], bL[3], &Bc[wn * 32 + lane][kk]);
            ldm_x4(bH[0], bH[1], bH[2], bH[3], &Bc[wn * 32 + lane][kk + 4]);
#pragma unroll
            for (int nt = 0; nt < 4; nt++) {
                unsigned bb[2] = { bL[nt], bH[nt] };
                mma_tf32(acc[0][nt], a0f, bb);
                mma_tf32(acc[1][nt], a1f, bb);
            }
        }
    }

    // epilogue
    if (mode == 0) {
#pragma unroll
        for (int mt = 0; mt < 2; mt++) {
            int r0 = bm + wm * 32 + mt * 16 + gid;
            int r1 = r0 + 8;
#pragma unroll
            for (int nt = 0; nt < 4; nt++) {
                int col0 = bn + wn * 32 + nt * 8 + tig * 2;
                int col1 = col0 + 1;
                float v0 = acc[mt][nt][0] * alpha;
                float v1 = acc[mt][nt][1] * alpha;
                float v2 = acc[mt][nt][2] * alpha;
                float v3 = acc[mt][nt][3] * alpha;
                if (col0 < N) {
                    if (Res) { v0 += Res[(size_t)r0 * N + col0]; v2 += Res[(size_t)r1 * N + col0]; }
                    C[(size_t)r0 * N + col0] = v0;
                    C[(size_t)r1 * N + col0] = v2;
                }
                if (col1 < N) {
                    if (Res) { v1 += Res[(size_t)r0 * N + col1]; v3 += Res[(size_t)r1 * N + col1]; }
                    C[(size_t)r0 * N + col1] = v1;
                    C[(size_t)r1 * N + col1] = v3;
                }
            }
        }
    } else {
        int No = N >> 1;
#pragma unroll
        for (int mt = 0; mt < 2; mt++) {
            int r0 = bm + wm * 32 + mt * 16 + gid;
            int r1 = r0 + 8;
#pragma unroll
            for (int nt = 0; nt < 4; nt++) {
                int col0 = bn + wn * 32 + nt * 8 + tig * 2;
                int outc = col0 >> 1;
                float h0 = acc[mt][nt][0], g0 = acc[mt][nt][1];
                float h2 = acc[mt][nt][2], g2 = acc[mt][nt][3];
                float o0, o2;
                if (mode == 1) {
                    o0 = h0 / (1.f + expf(-g0));
                    o2 = h2 / (1.f + expf(-g2));
                } else {
                    o0 = h0 / (1.f + expf(-h0)) * g0;
                    o2 = h2 / (1.f + expf(-h2)) * g2;
                }
                C[(size_t)r0 * No + outc] = o0;
                C[(size_t)r1 * No + outc] = o2;
            }
        }
    }
}

// ---------------- Windowed attention (valid rows) ----------------
__global__ __launch_bounds__(256) void win_attn(
    const float* __restrict__ qb, const float* __restrict__ kv,
    const float* __restrict__ qrel, const int* __restrict__ alen,
    float* __restrict__ ob)
{
    extern __shared__ float sm[];
    float* Qs = sm;                 // 64*65
    float* Ks = Qs + 64 * 65;       // 192*65
    float* Vs = Ks + 192 * 65;      // 192*65
    float* S  = Vs + 192 * 65;      // 64*193

    int c = blockIdx.x + 2;
    int h = blockIdx.y;
    int b = blockIdx.z;
    int cs = c * 64;
    int lim = alen[b] + LCW;
    if (cs >= lim) return;
    int tid = threadIdx.x;
    int g = h >> 2;

    const float* qbase = qb + ((size_t)(b * TP + cs)) * DD + h * 64;
#pragma unroll
    for (int i = 0; i < 4; i++) {
        int e = tid + i * 256;
        int row = e >> 4, dq = (e & 15) * 4;
        float4 v = *(const float4*)(qbase + (size_t)row * DD + dq);
        Qs[row * 65 + dq + 0] = v.x; Qs[row * 65 + dq + 1] = v.y;
        Qs[row * 65 + dq + 2] = v.z; Qs[row * 65 + dq + 3] = v.w;
    }
    const float* kbase = kv + ((size_t)(b * TP + cs - 128)) * 256 + g * 64;
    const float* vbase = kbase + 128;
#pragma unroll
    for (int i = 0; i < 12; i++) {
        int e = tid + i * 256;
        int row = e >> 4, dq = (e & 15) * 4;
        float4 kk = *(const float4*)(kbase + (size_t)row * 256 + dq);
        Ks[row * 65 + dq + 0] = kk.x; Ks[row * 65 + dq + 1] = kk.y;
        Ks[row * 65 + dq + 2] = kk.z; Ks[row * 65 + dq + 3] = kk.w;
        float4 vv = *(const float4*)(vbase + (size_t)row * 256 + dq);
        Vs[row * 65 + dq + 0] = vv.x; Vs[row * 65 + dq + 1] = vv.y;
        Vs[row * 65 + dq + 2] = vv.z; Vs[row * 65 + dq + 3] = vv.w;
    }
    __syncthreads();

    int tx = tid & 15, ty = tid >> 4;
#pragma unroll
    for (int rr = 0; rr < 4; rr++) {
        int r = rr * 16 + ty;
        size_t qr = ((size_t)(b * TP + cs + r) * HH + h) * 383;
#pragma unroll
        for (int jj = 0; jj < 12; jj++) {
            int j = jj * 16 + tx;
            float acc = 0.f;
#pragma unroll
            for (int d = 0; d < 64; d++) acc += Qs[r * 65 + d] * Ks[j * 65 + d];
            int kk = cs - 128 + j;
            float s = (kk < lim) ? (acc + __ldg(&qrel[qr + 319 + r - j])) : NEGINF;
            S[r * 193 + j] = s;
        }
    }
    __syncthreads();

    int lane = tid & 31, wid = tid >> 5;
#pragma unroll
    for (int rw = 0; rw < 8; rw++) {
        int r = rw * 8 + wid;
        float sv[6];
        float m = NEGINF;
#pragma unroll
        for (int t = 0; t < 6; t++) { sv[t] = S[r * 193 + lane + t * 32]; m = fmaxf(m, sv[t]); }
#pragma unroll
        for (int o = 16; o > 0; o >>= 1) m = fmaxf(m, __shfl_xor_sync(0xffffffffu, m, o));
        float ss = 0.f;
#pragma unroll
        for (int t = 0; t < 6; t++) { sv[t] = expf(sv[t] - m); ss += sv[t]; }
#pragma unroll
        for (int o = 16; o > 0; o >>= 1) ss += __shfl_xor_sync(0xffffffffu, ss, o);
        float inv = 1.f / ss;
#pragma unroll
        for (int t = 0; t < 6; t++) S[r * 193 + lane + t * 32] = sv[t] * inv;
    }
    __syncthreads();

#pragma unroll
    for (int rr = 0; rr < 4; rr++) {
        int r = rr * 16 + ty;
        int q = cs + r;
        int d0 = tx * 4;
        float a0 = 0.f, a1 = 0.f, a2 = 0.f, a3 = 0.f;
#pragma unroll 4
        for (int j = 0; j < 192; j++) {
            float p = S[r * 193 + j];
            a0 += p * Vs[j * 65 + d0 + 0];
            a1 += p * Vs[j * 65 + d0 + 1];
            a2 += p * Vs[j * 65 + d0 + 2];
            a3 += p * Vs[j * 65 + d0 + 3];
        }
        if (q < lim) {
            float* op = ob + ((size_t)(b * TT + q - 128)) * DD + h * 64 + d0;
            op[0] = a0; op[1] = a1; op[2] = a2; op[3] = a3;
        }
    }
}

// ---------------- Dense flash attention (invalid rows, chunked) ----------------
__global__ __launch_bounds__(256) void dense_flash(
    const float* __restrict__ qb, const float* __restrict__ kv,
    const float* __restrict__ qrel, const int* __restrict__ alen,
    float* __restrict__ ob)
{
    extern __shared__ float sm[];
    float* Qs = sm;                  // 64*65
    float* Ks = Qs + 64 * 65;        // 128*65
    float* Vs = Ks + 128 * 65;       // 128*65
    float* S  = Vs + 128 * 65;       // 64*132
    float* rowm  = S + 64 * 132;
    float* rowsum = rowm + 64;
    float* rowscale = rowsum + 64;

    int c = blockIdx.x + 2;
    int h = blockIdx.y;
    int b = blockIdx.z;
    int cs = c * 64;
    int lim = alen[b] + LCW;
    if (cs + 64 <= lim) return;
    int tid = threadIdx.x;
    int g = h >> 2;
    int tx = tid & 15, ty = tid >> 4;
    int lane = tid & 31, wd = tid >> 5;

    const float* qbase = qb + ((size_t)(b * TP + cs)) * DD + h * 64;
#pragma unroll
    for (int i = 0; i < 4; i++) {
        int e = tid + i * 256;
        int row = e >> 4, dq = (e & 15) * 4;
        float4 v = *(const float4*)(qbase + (size_t)row * DD + dq);
        Qs[row * 65 + dq + 0] = v.x; Qs[row * 65 + dq + 1] = v.y;
        Qs[row * 65 + dq + 2] = v.z; Qs[row * 65 + dq + 3] = v.w;
    }
    if (tid < 64) { rowm[tid] = NEGINF; rowsum[tid] = 0.f; }

    float acc[4][4];
#pragma unroll
    for (int rr = 0; rr < 4; rr++)
#pragma unroll
        for (int q4 = 0; q4 < 4; q4++) acc[rr][q4] = 0.f;

    __syncthreads();

    for (int pg = 0; pg < 9; pg++) {
        const float* kp = kv + ((size_t)(b * TP + pg * 128)) * 256 + g * 64;
#pragma unroll
        for (int i = 0; i < 8; i++) {
            int e = tid + i * 256;
            int row = e >> 4, dq = (e & 15) * 4;
            float4 kk = *(const float4*)(kp + (size_t)row * 256 + dq);
            Ks[row * 65 + dq + 0] = kk.x; Ks[row * 65 + dq + 1] = kk.y;
            Ks[row * 65 + dq + 2] = kk.z; Ks[row * 65 + dq + 3] = kk.w;
            float4 vv = *(const float4*)(kp + (size_t)row * 256 + 128 + dq);
            Vs[row * 65 + dq + 0] = vv.x; Vs[row * 65 + dq + 1] = vv.y;
            Vs[row * 65 + dq + 2] = vv.z; Vs[row * 65 + dq + 3] = vv.w;
        }
        __syncthreads();

        float accS[4][8];
#pragma unroll
        for (int rr = 0; rr < 4; rr++)
#pragma unroll
            for (int jj = 0; jj < 8; jj++) accS[rr][jj] = 0.f;
#pragma unroll 8
        for (int d = 0; d < 64; d++) {
            float kvv[8];
#pragma unroll
            for (int jj = 0; jj < 8; jj++) kvv[jj] = Ks[(jj * 16 + tx) * 65 + d];
#pragma unroll
            for (int rr = 0; rr < 4; rr++) {
                float qv = Qs[(rr * 16 + ty) * 65 + d];
#pragma unroll
                for (int jj = 0; jj < 8; jj++) accS[rr][jj] += qv * kvv[jj];
            }
        }
#pragma unroll
        for (int rr = 0; rr < 4; rr++) {
            int r = rr * 16 + ty;
            int q = cs + r;
            size_t qr = ((size_t)(b * TP + q) * HH + h) * 383;
#pragma unroll
            for (int jj = 0; jj < 8; jj++) {
                int j = jj * 16 + tx;
                int k = pg * 128 + j;
                int dist = q - k;
                dist = max(-191, min(191, dist));
                S[r * 132 + j] = accS[rr][jj] + __ldg(&qrel[qr + 191 + dist]);
            }
        }
        __syncthreads();

#pragma unroll
        for (int rw = 0; rw < 8; rw++) {
            int r = wd * 8 + rw;
            float v0 = S[r * 132 + lane];
            float v1 = S[r * 132 + lane + 32];
            float v2 = S[r * 132 + lane + 64];
            float v3 = S[r * 132 + lane + 96];
            float mn = fmaxf(fmaxf(v0, v1), fmaxf(v2, v3));
#pragma unroll
            for (int o = 16; o > 0; o >>= 1) mn = fmaxf(mn, __shfl_xor_sync(0xffffffffu, mn, o));
            float mo = rowm[r];
            float mp = fmaxf(mo, mn);
            float p0 = expf(v0 - mp), p1 = expf(v1 - mp), p2 = expf(v2 - mp), p3 = expf(v3 - mp);
            S[r * 132 + lane] = p0; S[r * 132 + lane + 32] = p1;
            S[r * 132 + lane + 64] = p2; S[r * 132 + lane + 96] = p3;
            float ss = p0 + p1 + p2 + p3;
#pragma unroll
            for (int o = 16; o > 0; o >>= 1) ss += __shfl_xor_sync(0xffffffffu, ss, o);
            if (lane == 0) {
                float scale = expf(mo - mp);
                rowm[r] = mp;
                rowscale[r] = scale;
                rowsum[r] = rowsum[r] * scale + ss;
            }
        }
        __syncthreads();

        int d0 = tx * 4;
#pragma unroll
        for (int rr = 0; rr < 4; rr++) {
            int r = rr * 16 + ty;
            float sc = rowscale[r];
#pragma unroll
            for (int q4 = 0; q4 < 4; q4++) acc[rr][q4] *= sc;
        }
#pragma unroll 4
        for (int j = 0; j < 128; j++) {
            float w0 = Vs[j * 65 + d0 + 0];
            float w1 = Vs[j * 65 + d0 + 1];
            float w2 = Vs[j * 65 + d0 + 2];
            float w3 = Vs[j * 65 + d0 + 3];
#pragma unroll
            for (int rr = 0; rr < 4; rr++) {
                float p = S[(rr * 16 + ty) * 132 + j];
                acc[rr][0] += p * w0; acc[rr][1] += p * w1;
                acc[rr][2] += p * w2; acc[rr][3] += p * w3;
            }
        }
        __syncthreads();
    }

    int d0 = tx * 4;
#pragma unroll
    for (int rr = 0; rr < 4; rr++) {
        int r = rr * 16 + ty;
        int q = cs + r;
        if (q >= lim) {
            float inv = 1.f / rowsum[r];
            float* op = ob + ((size_t)(b * TT + q - 128)) * DD + h * 64 + d0;
            op[0] = acc[rr][0] * inv;
            op[1] = acc[rr][1] * inv;
            op[2] = acc[rr][2] * inv;
            op[3] = acc[rr][3] * inv;
        }
    }
}

// ---------------- depthwise conv (k=9, pad 4) + SiLU ----------------
__global__ __launch_bounds__(128) void dwconv_silu(
    const float* __restrict__ in, const float* __restrict__ dw, float* __restrict__ out)
{
    int t = blockIdx.x, b = blockIdx.y;
    int d0 = threadIdx.x * 4;
    float w[9][4];
#pragma unroll
    for (int c = 0; c < 4; c++)
#pragma unroll
        for (int j = 0; j < 9; j++)
            w[j][c] = __ldg(&dw[(d0 + c) * 9 + j]);
    float4 acc = make_float4(0.f, 0.f, 0.f, 0.f);
#pragma unroll
    for (int j = 0; j < 9; j++) {
        int tt = t + j - 4;
        if (tt >= 0 && tt < TT) {
            float4 v = *(const float4*)(in + ((size_t)(b * TT + tt)) * DD + d0);
            acc.x += v.x * w[j][0];
            acc.y += v.y * w[j][1];
            acc.z += v.z * w[j][2];
            acc.w += v.w * w[j][3];
        }
    }
    acc.x = acc.x / (1.f + expf(-acc.x));
    acc.y = acc.y / (1.f + expf(-acc.y));
    acc.z = acc.z / (1.f + expf(-acc.z));
    acc.w = acc.w / (1.f + expf(-acc.w));
    *(float4*)(out + ((size_t)(b * TT + t)) * DD + d0) = acc;
}

// ---------------- orchestration ----------------
extern "C" void kernel_launch(void* const* d_in, const int* in_sizes, int n_in,
                              void* d_out, int out_size)
{
    const float* x_in  = (const float*)d_in[0];
    const int*   alen  = (const int*)d_in[1];
    const float* ln1_w = (const float*)d_in[2];
    const float* ln1_b = (const float*)d_in[3];
    const float* wq    = (const float*)d_in[4];
    const float* wk    = (const float*)d_in[5];
    const float* wv    = (const float*)d_in[6];
    const float* wo    = (const float*)d_in[7];
    const float* rel   = (const float*)d_in[8];
    const float* ln2_w = (const float*)d_in[9];
    const float* ln2_b = (const float*)d_in[10];
    const float* pw1   = (const float*)d_in[11];
    const float* dw    = (const float*)d_in[12];
    const float* pw2   = (const float*)d_in[13];
    const float* ln3_w = (const float*)d_in[14];
    const float* ln3_b = (const float*)d_in[15];
    const float* w1    = (const float*)d_in[16];
    const float* w2    = (const float*)d_in[17];

    float* scr = nullptr;
    cudaGetSymbolAddress((void**)&scr, g_scr);
    float* xpad  = scr + OFF_XPAD;
    float* xbuf  = scr + OFF_XBUF;
    float* ybuf  = scr + OFF_YBUF;
    float* qbuf  = scr + OFF_QBUF;
    float* kvbuf = scr + OFF_KVBUF;
    float* qrlb  = scr + OFF_QREL;
    float* obuf  = scr + OFF_OBUF;
    float* hbuf  = scr + OFF_HBUF;
    float* gbuf  = scr + OFF_GBUF;
    float* kvw   = scr + OFF_KVW;
    float* pw1p  = scr + OFF_PW1P;
    float* w1p   = scr + OFF_W1P;

    const int WIN_SMEM = (64 * 65 + 192 * 65 + 192 * 65 + 64 * 193) * 4;
    const int DF_SMEM  = (64 * 65 + 128 * 65 + 128 * 65 + 64 * 132 + 192) * 4;
    cudaFuncSetAttribute(win_attn, cudaFuncAttributeMaxDynamicSharedMemorySize, WIN_SMEM);
    cudaFuncSetAttribute(dense_flash, cudaFuncAttributeMaxDynamicSharedMemorySize, DF_SMEM);

    zero_pad_kernel<<<(BB * LCW * DD + 255) / 256, 256>>>(xpad);
    pack_kv<<<(4 * 256 * 512 + 255) / 256, 256>>>(wk, wv, kvw);
    pack_glu<<<(4 * 1024 * 512 + 255) / 256, 256>>>(pw1, pw1p, 512, 4 * 1024 * 512);
    pack_glu<<<(4 * 2048 * 512 + 255) / 256, 256>>>(w1, w1p, 1024, 4 * 2048 * 512);

    for (int l = 0; l < 4; l++) {
        const float* src = (l == 0) ? x_in : xbuf;
        ln_kernel<<<4096, 128>>>(src, ln1_w + l * 512, ln1_b + l * 512, ybuf, xpad);
        gemm_tc<<<dim3(8, 36), 256>>>(xpad, wq + (size_t)l * 512 * 512, qbuf, nullptr, 4608, 512, 512, 0.125f, 0);
        gemm_tc<<<dim3(4, 36), 256>>>(xpad, kvw + (size_t)l * 256 * 512, kvbuf, nullptr, 4608, 256, 512, 1.f, 0);
        gemm_tc<<<dim3(6, 288), 256>>>(qbuf, rel + (size_t)l * 383 * 64, qrlb, nullptr, 36864, 383, 64, 1.f, 0);
        win_attn<<<dim3(16, 8, 4), 256, WIN_SMEM>>>(qbuf, kvbuf, qrlb, alen, obuf);
        dense_flash<<<dim3(16, 8, 4), 256, DF_SMEM>>>(qbuf, kvbuf, qrlb, alen, obuf);
        gemm_tc<<<dim3(8, 32), 256>>>(obuf, wo + (size_t)l * 512 * 512, xbuf, ybuf, 4096, 512, 512, 1.f, 0);
        // conv module: pw1 GEMM with fused GLU -> gbuf[4096x512]
        ln_kernel<<<4096, 128>>>(xbuf, ln2_w + l * 512, ln2_b + l * 512, ybuf, nullptr);
        gemm_tc<<<dim3(16, 32), 256>>>(ybuf, pw1p + (size_t)l * 1024 * 512, gbuf, nullptr, 4096, 1024, 512, 1.f, 1);
        dwconv_silu<<<dim3(1024, 4), 128>>>(gbuf, dw + (size_t)l * 512 * 9, hbuf);
        gemm_tc<<<dim3(8, 32), 256>>>(hbuf, pw2 + (size_t)l * 512 * 512, xbuf, ybuf, 4096, 512, 512, 1.f, 0);
        // FFN: w1 GEMM with fused SwiGLU -> gbuf[4096x1024]
        ln_kernel<<<4096, 128>>>(xbuf, ln3_w + l * 512, ln3_b + l * 512, ybuf, nullptr);
        gemm_tc<<<dim3(32, 32), 256>>>(ybuf, w1p + (size_t)l * 2048 * 512, gbuf, nullptr, 4096, 2048, 512, 1.f, 2);
        float* dst = (l == 3) ? (float*)d_out : xbuf;
        gemm_tc<<<dim3(8, 32), 256>>>(gbuf, w2 + (size_t)l * 512 * 1024, dst, ybuf, 4096, 512, 1024, 1.f, 0);
    }
}

// round 6
// speedup vs baseline: 4.1190x; 1.5662x over previous
#include <cuda_runtime.h>
#include <math.h>

#define TT 1024
#define BB 4
#define DD 512
#define HH 8
#define TP 1152
#define LCW 128
#define NEGINF (__int_as_float(0xff800000))

// ---------------- scratch (static device memory) ----------------
#define OFF_XPAD  0UL          // 4*1152*512  = 2359296
#define OFF_XBUF  2359296UL    // 2097152
#define OFF_YBUF  4456448UL    // 2097152
#define OFF_QBUF  6553600UL    // 4608*512    = 2359296
#define OFF_KVBUF 8912896UL    // 4608*256    = 1179648
#define OFF_QREL  10092544UL   // 36864*383   = 14118912
#define OFF_OBUF  24211456UL   // 2097152
#define OFF_HBUF  26308608UL   // 8388608
#define OFF_GBUF  34697216UL   // 4194304
#define OFF_KVW   38891520UL   // 4*256*512   = 524288
#define OFF_PW1P  39415808UL   // 4*1024*512  = 2097152
#define OFF_W1P   41512960UL   // 4*2048*512  = 4194304
#define SCR_TOTAL 45707264UL

__device__ float g_scr[SCR_TOTAL];

// ---------------- cp.async / ldmatrix helpers ----------------
__device__ __forceinline__ void cpa16(void* smem, const void* g) {
    unsigned s = (unsigned)__cvta_generic_to_shared(smem);
    asm volatile("cp.async.ca.shared.global [%0], [%1], 16;" :: "r"(s), "l"(g));
}
__device__ __forceinline__ void cpa16p(void* smem, const void* g, bool pred) {
    unsigned s = (unsigned)__cvta_generic_to_shared(smem);
    int sz = pred ? 16 : 0;
    asm volatile("cp.async.ca.shared.global [%0], [%1], 16, %2;" :: "r"(s), "l"(g), "r"(sz));
}
__device__ __forceinline__ void cp_commit() {
    asm volatile("cp.async.commit_group;");
}
template <int N>
__device__ __forceinline__ void cp_wait() {
    asm volatile("cp.async.wait_group %0;" :: "n"(N));
}
__device__ __forceinline__ void ldm_x4(unsigned& r0, unsigned& r1, unsigned& r2, unsigned& r3,
                                       const void* p) {
    unsigned a = (unsigned)__cvta_generic_to_shared(p);
    asm volatile("ldmatrix.sync.aligned.m8n8.x4.shared.b16 {%0,%1,%2,%3}, [%4];"
                 : "=r"(r0), "=r"(r1), "=r"(r2), "=r"(r3) : "r"(a));
}
__device__ __forceinline__ void mma_tf32(float* c, const unsigned* a, const unsigned* b) {
    asm volatile(
        "mma.sync.aligned.m16n8k8.row.col.f32.tf32.tf32.f32 "
        "{%0,%1,%2,%3}, {%4,%5,%6,%7}, {%8,%9}, {%0,%1,%2,%3};"
        : "+f"(c[0]), "+f"(c[1]), "+f"(c[2]), "+f"(c[3])
        : "r"(a[0]), "r"(a[1]), "r"(a[2]), "r"(a[3]), "r"(b[0]), "r"(b[1]));
}

// ---------------- zero the left-context pad rows of xpad ----------------
__global__ void zero_pad_kernel(float* __restrict__ xpad) {
    int i = blockIdx.x * 256 + threadIdx.x;
    if (i < BB * LCW * DD) {
        int b = i / (LCW * DD);
        int rem = i - b * (LCW * DD);
        xpad[(size_t)b * TP * DD + rem] = 0.f;
    }
}

// ---------------- pack K/V weights: kvw[l][256][512] ----------------
__global__ void pack_kv(const float* __restrict__ wk, const float* __restrict__ wv,
                        float* __restrict__ kvw)
{
    int i = blockIdx.x * 256 + threadIdx.x;
    if (i >= 4 * 256 * 512) return;
    int l = i / (256 * 512);
    int r = (i / 512) % 256;
    int c = i % 512;
    float v = (r < 128) ? wk[(size_t)l * 128 * 512 + r * 512 + c]
                        : wv[(size_t)l * 128 * 512 + (r - 128) * 512 + c];
    kvw[i] = v;
}

// ---------------- interleave GLU weight halves ----------------
__global__ void pack_glu(const float* __restrict__ w, float* __restrict__ wp,
                         int half, int total)
{
    int i = blockIdx.x * 256 + threadIdx.x;
    if (i >= total) return;
    int per = 2 * half * 512;
    int l = i / per;
    int rem = i - l * per;
    int r = rem / 512;
    int c = rem - r * 512;
    int src = (r & 1) ? (half + (r >> 1)) : (r >> 1);
    wp[i] = w[(size_t)l * per + (size_t)src * 512 + c];
}

// ---------------- LayerNorm ----------------
__global__ __launch_bounds__(128) void ln_kernel(
    const float* __restrict__ x, const float* __restrict__ w,
    const float* __restrict__ bvec, float* __restrict__ out,
    float* __restrict__ outpad)
{
    __shared__ float red[8];
    int r = blockIdx.x;
    int tid = threadIdx.x;
    const float* xr = x + (size_t)r * DD;
    float4 v = *(const float4*)(xr + tid * 4);
    float s  = v.x + v.y + v.z + v.w;
    float sq = v.x * v.x + v.y * v.y + v.z * v.z + v.w * v.w;
#pragma unroll
    for (int o = 16; o > 0; o >>= 1) {
        s  += __shfl_xor_sync(0xffffffffu, s, o);
        sq += __shfl_xor_sync(0xffffffffu, sq, o);
    }
    int warp = tid >> 5;
    if ((tid & 31) == 0) { red[warp] = s; red[4 + warp] = sq; }
    __syncthreads();
    float ts = red[0] + red[1] + red[2] + red[3];
    float tq = red[4] + red[5] + red[6] + red[7];
    float mean = ts * (1.f / DD);
    float var  = tq * (1.f / DD) - mean * mean;
    float inv  = rsqrtf(var + 1e-4f);
    float4 wv = *(const float4*)(w + tid * 4);
    float4 bv = *(const float4*)(bvec + tid * 4);
    float4 o;
    o.x = (v.x - mean) * inv * wv.x + bv.x;
    o.y = (v.y - mean) * inv * wv.y + bv.y;
    o.z = (v.z - mean) * inv * wv.z + bv.z;
    o.w = (v.w - mean) * inv * wv.w + bv.w;
    *(float4*)(out + (size_t)r * DD + tid * 4) = o;
    if (outpad) {
        int b = r >> 10, t = r & 1023;
        *(float4*)(outpad + ((size_t)(b * TP + LCW + t)) * DD + tid * 4) = o;
    }
}

// ---------------- TF32 tensor-core GEMM, 3-stage cp.async + ldmatrix ----------------
__global__ __launch_bounds__(256) void gemm_tc(
    const float* __restrict__ A, const float* __restrict__ B,
    float* __restrict__ C, const float* __restrict__ Res,
    int M, int N, int K, float alpha, int mode)
{
    __shared__ float As[3][128][20];
    __shared__ float Bs[3][64][20];

    int tid = threadIdx.x;
    int bm = blockIdx.y * 128;
    int bn = blockIdx.x * 64;
    int wid = tid >> 5, lane = tid & 31;
    int wm = wid & 3, wn = wid >> 2;
    int gid = lane >> 2, tig = lane & 3;

    float acc[2][4][4];
#pragma unroll
    for (int i = 0; i < 2; i++)
#pragma unroll
        for (int j = 0; j < 4; j++)
#pragma unroll
            for (int q = 0; q < 4; q++) acc[i][j][q] = 0.f;

    int ar[2], ac[2];
#pragma unroll
    for (int i = 0; i < 2; i++) {
        int idx = tid + i * 256;
        ar[i] = idx >> 2;
        ac[i] = (idx & 3) * 4;
    }
    int brow = tid >> 2;
    int bc   = (tid & 3) * 4;
    bool bpred = (bn + brow < N);

    const float* ap0 = A + (size_t)(bm + ar[0]) * K + ac[0];
    const float* ap1 = A + (size_t)(bm + ar[1]) * K + ac[1];
    const float* bp  = B + (size_t)(bn + brow) * K + bc;

    int nIters = K >> 4;
    int aRow = lane & 15;
    int aCol = (lane < 16) ? 0 : 4;

    cpa16(&As[0][ar[0]][ac[0]], ap0);
    cpa16(&As[0][ar[1]][ac[1]], ap1);
    cpa16p(&Bs[0][brow][bc], bp, bpred);
    cp_commit();
    if (nIters > 1) {
        cpa16(&As[1][ar[0]][ac[0]], ap0 + 16);
        cpa16(&As[1][ar[1]][ac[1]], ap1 + 16);
        cpa16p(&Bs[1][brow][bc], bp + 16, bpred);
    }
    cp_commit();

    for (int t = 0; t < nIters; t++) {
        cp_wait<1>();
        __syncthreads();
        if (t + 2 < nIters) {
            int k0 = (t + 2) << 4;
            int st = (t + 2) % 3;
            cpa16(&As[st][ar[0]][ac[0]], ap0 + k0);
            cpa16(&As[st][ar[1]][ac[1]], ap1 + k0);
            cpa16p(&Bs[st][brow][bc], bp + k0, bpred);
        }
        cp_commit();

        int cur = t % 3;
        const float (*Ac)[20] = As[cur];
        const float (*Bc)[20] = Bs[cur];
#pragma unroll
        for (int ks = 0; ks < 2; ks++) {
            int kk = ks * 8;
            unsigned a0f[4], a1f[4], bL[4], bH[4];
            ldm_x4(a0f[0], a0f[1], a0f[2], a0f[3], &Ac[wm * 32 + aRow][kk + aCol]);
            ldm_x4(a1f[0], a1f[1], a1f[2], a1f[3], &Ac[wm * 32 + 16 + aRow][kk + aCol]);
            ldm_x4(bL[0], bL[1], bL[2], bL[3], &Bc[wn * 32 + lane][kk]);
            ldm_x4(bH[0], bH[1], bH[2], bH[3], &Bc[wn * 32 + lane][kk + 4]);
#pragma unroll
            for (int nt = 0; nt < 4; nt++) {
                unsigned bb[2] = { bL[nt], bH[nt] };
                mma_tf32(acc[0][nt], a0f, bb);
                mma_tf32(acc[1][nt], a1f, bb);
            }
        }
    }

    if (mode == 0) {
#pragma unroll
        for (int mt = 0; mt < 2; mt++) {
            int r0 = bm + wm * 32 + mt * 16 + gid;
            int r1 = r0 + 8;
#pragma unroll
            for (int nt = 0; nt < 4; nt++) {
                int col0 = bn + wn * 32 + nt * 8 + tig * 2;
                int col1 = col0 + 1;
                float v0 = acc[mt][nt][0] * alpha;
                float v1 = acc[mt][nt][1] * alpha;
                float v2 = acc[mt][nt][2] * alpha;
                float v3 = acc[mt][nt][3] * alpha;
                if (col0 < N) {
                    if (Res) { v0 += Res[(size_t)r0 * N + col0]; v2 += Res[(size_t)r1 * N + col0]; }
                    C[(size_t)r0 * N + col0] = v0;
                    C[(size_t)r1 * N + col0] = v2;
                }
                if (col1 < N) {
                    if (Res) { v1 += Res[(size_t)r0 * N + col1]; v3 += Res[(size_t)r1 * N + col1]; }
                    C[(size_t)r0 * N + col1] = v1;
                    C[(size_t)r1 * N + col1] = v3;
                }
            }
        }
    } else {
        int No = N >> 1;
#pragma unroll
        for (int mt = 0; mt < 2; mt++) {
            int r0 = bm + wm * 32 + mt * 16 + gid;
            int r1 = r0 + 8;
#pragma unroll
            for (int nt = 0; nt < 4; nt++) {
                int col0 = bn + wn * 32 + nt * 8 + tig * 2;
                int outc = col0 >> 1;
                float h0 = acc[mt][nt][0], g0 = acc[mt][nt][1];
                float h2 = acc[mt][nt][2], g2 = acc[mt][nt][3];
                float o0, o2;
                if (mode == 1) {
                    o0 = h0 / (1.f + expf(-g0));
                    o2 = h2 / (1.f + expf(-g2));
                } else {
                    o0 = h0 / (1.f + expf(-h0)) * g0;
                    o2 = h2 / (1.f + expf(-h2)) * g2;
                }
                C[(size_t)r0 * No + outc] = o0;
                C[(size_t)r1 * No + outc] = o2;
            }
        }
    }
}

// ---------------- Windowed attention (valid rows), tf32 tensor cores ----------------
// grid (16, 8, 4), 256 threads. Smem: Qs[64][68], Ks[192][68], Vt[64][196], S[64][196]
__global__ __launch_bounds__(256) void win_attn(
    const float* __restrict__ qb, const float* __restrict__ kv,
    const float* __restrict__ qrel, const int* __restrict__ alen,
    float* __restrict__ ob)
{
    extern __shared__ float sm[];
    float* Qs = sm;                    // 64*68   = 4352
    float* Ks = Qs + 64 * 68;          // 192*68  = 13056
    float* Vt = Ks + 192 * 68;         // 64*196  = 12544 (transposed V: [dim][key])
    float* S  = Vt + 64 * 196;         // 64*196  = 12544

    int c = blockIdx.x + 2;
    int h = blockIdx.y;
    int b = blockIdx.z;
    int cs = c * 64;
    int lim = alen[b] + LCW;
    if (cs >= lim) return;
    int tid = threadIdx.x;
    int g = h >> 2;
    int lane = tid & 31, wid = tid >> 5;
    int wm = wid & 3, wn = wid >> 2;       // 4 x 2
    int gid = lane >> 2, tig = lane & 3;
    int aRow = lane & 15, aCol = (lane < 16) ? 0 : 4;

    const float* qbase = qb + ((size_t)(b * TP + cs)) * DD + h * 64;
#pragma unroll
    for (int i = 0; i < 4; i++) {
        int e = tid + i * 256;
        int row = e >> 4, dq = (e & 15) * 4;
        float4 v = *(const float4*)(qbase + (size_t)row * DD + dq);
        Qs[row * 68 + dq + 0] = v.x; Qs[row * 68 + dq + 1] = v.y;
        Qs[row * 68 + dq + 2] = v.z; Qs[row * 68 + dq + 3] = v.w;
    }
    const float* kbase = kv + ((size_t)(b * TP + cs - 128)) * 256 + g * 64;
    const float* vbase = kbase + 128;
#pragma unroll
    for (int i = 0; i < 12; i++) {
        int e = tid + i * 256;
        int row = e >> 4, dq = (e & 15) * 4;
        float4 kk = *(const float4*)(kbase + (size_t)row * 256 + dq);
        Ks[row * 68 + dq + 0] = kk.x; Ks[row * 68 + dq + 1] = kk.y;
        Ks[row * 68 + dq + 2] = kk.z; Ks[row * 68 + dq + 3] = kk.w;
        float4 vv = *(const float4*)(vbase + (size_t)row * 256 + dq);
        Vt[(dq + 0) * 196 + row] = vv.x; Vt[(dq + 1) * 196 + row] = vv.y;
        Vt[(dq + 2) * 196 + row] = vv.z; Vt[(dq + 3) * 196 + row] = vv.w;
    }
    __syncthreads();

    // ---- S = Q @ K^T  (warp tile 16 x 96) ----
    float accS[12][4];
#pragma unroll
    for (int i = 0; i < 12; i++)
#pragma unroll
        for (int j = 0; j < 4; j++) accS[i][j] = 0.f;

#pragma unroll
    for (int ks = 0; ks < 8; ks++) {
        int kk = ks * 8;
        unsigned a[4];
        ldm_x4(a[0], a[1], a[2], a[3], &Qs[(wm * 16 + aRow) * 68 + kk + aCol]);
#pragma unroll
        for (int ng = 0; ng < 3; ng++) {
            int n0 = wn * 96 + ng * 32;
            unsigned bL[4], bH[4];
            ldm_x4(bL[0], bL[1], bL[2], bL[3], &Ks[(n0 + lane) * 68 + kk]);
            ldm_x4(bH[0], bH[1], bH[2], bH[3], &Ks[(n0 + lane) * 68 + kk + 4]);
#pragma unroll
            for (int t2 = 0; t2 < 4; t2++) {
                unsigned bb[2] = { bL[t2], bH[t2] };
                mma_tf32(accS[ng * 4 + t2], a, bb);
            }
        }
    }

    // bias + mask, spill to smem
    int r0 = wm * 16 + gid, r1 = r0 + 8;
    size_t qr0 = ((size_t)(b * TP + cs + r0) * HH + h) * 383;
    size_t qr1 = ((size_t)(b * TP + cs + r1) * HH + h) * 383;
#pragma unroll
    for (int nt = 0; nt < 12; nt++) {
        int c0 = wn * 96 + nt * 8 + tig * 2;
        int c1 = c0 + 1;
        int k0g = cs - 128 + c0;
        int k1g = k0g + 1;
        S[r0 * 196 + c0] = (k0g < lim) ? (accS[nt][0] + __ldg(&qrel[qr0 + 319 + r0 - c0])) : NEGINF;
        S[r0 * 196 + c1] = (k1g < lim) ? (accS[nt][1] + __ldg(&qrel[qr0 + 319 + r0 - c1])) : NEGINF;
        S[r1 * 196 + c0] = (k0g < lim) ? (accS[nt][2] + __ldg(&qrel[qr1 + 319 + r1 - c0])) : NEGINF;
        S[r1 * 196 + c1] = (k1g < lim) ? (accS[nt][3] + __ldg(&qrel[qr1 + 319 + r1 - c1])) : NEGINF;
    }
    __syncthreads();

    // softmax per row (warp per 8 rows)
#pragma unroll
    for (int rw = 0; rw < 8; rw++) {
        int r = wid * 8 + rw;
        float sv[6];
        float m = NEGINF;
#pragma unroll
        for (int t = 0; t < 6; t++) { sv[t] = S[r * 196 + lane + t * 32]; m = fmaxf(m, sv[t]); }
#pragma unroll
        for (int o = 16; o > 0; o >>= 1) m = fmaxf(m, __shfl_xor_sync(0xffffffffu, m, o));
        float ss = 0.f;
#pragma unroll
        for (int t = 0; t < 6; t++) { sv[t] = expf(sv[t] - m); ss += sv[t]; }
#pragma unroll
        for (int o = 16; o > 0; o >>= 1) ss += __shfl_xor_sync(0xffffffffu, ss, o);
        float inv = 1.f / ss;
#pragma unroll
        for (int t = 0; t < 6; t++) S[r * 196 + lane + t * 32] = sv[t] * inv;
    }
    __syncthreads();

    // ---- O = P @ V  via Vt (warp tile 16 x 32, k = 192) ----
    float accO[4][4];
#pragma unroll
    for (int i = 0; i < 4; i++)
#pragma unroll
        for (int j = 0; j < 4; j++) accO[i][j] = 0.f;

#pragma unroll
    for (int ks = 0; ks < 24; ks++) {
        int kk = ks * 8;
        unsigned a[4], bL[4], bH[4];
        ldm_x4(a[0], a[1], a[2], a[3], &S[(wm * 16 + aRow) * 196 + kk + aCol]);
        ldm_x4(bL[0], bL[1], bL[2], bL[3], &Vt[(wn * 32 + lane) * 196 + kk]);
        ldm_x4(bH[0], bH[1], bH[2], bH[3], &Vt[(wn * 32 + lane) * 196 + kk + 4]);
#pragma unroll
        for (int nt = 0; nt < 4; nt++) {
            unsigned bb[2] = { bL[nt], bH[nt] };
            mma_tf32(accO[nt], a, bb);
        }
    }

    int q0 = cs + r0, q1 = cs + r1;
#pragma unroll
    for (int nt = 0; nt < 4; nt++) {
        int d0 = wn * 32 + nt * 8 + tig * 2;
        if (q0 < lim) {
            float* op = ob + ((size_t)(b * TT + q0 - 128)) * DD + h * 64 + d0;
            op[0] = accO[nt][0]; op[1] = accO[nt][1];
        }
        if (q1 < lim) {
            float* op = ob + ((size_t)(b * TT + q1 - 128)) * DD + h * 64 + d0;
            op[0] = accO[nt][2]; op[1] = accO[nt][3];
        }
    }
}

// ---------------- Dense flash attention (invalid rows), tf32 tensor cores ----------------
// Smem: Qs[64][68], Ks[128][68], Vt[64][132], S[64][132], rowm/rowsum/rowscale[64]
__global__ __launch_bounds__(256) void dense_flash(
    const float* __restrict__ qb, const float* __restrict__ kv,
    const float* __restrict__ qrel, const int* __restrict__ alen,
    float* __restrict__ ob)
{
    extern __shared__ float sm[];
    float* Qs = sm;                    // 64*68
    float* Ks = Qs + 64 * 68;          // 128*68
    float* Vt = Ks + 128 * 68;         // 64*132 (transposed)
    float* S  = Vt + 64 * 132;         // 64*132
    float* rowm = S + 64 * 132;
    float* rowsum = rowm + 64;
    float* rowscale = rowsum + 64;

    int c = blockIdx.x + 2;
    int h = blockIdx.y;
    int b = blockIdx.z;
    int cs = c * 64;
    int lim = alen[b] + LCW;
    if (cs + 64 <= lim) return;
    int tid = threadIdx.x;
    int g = h >> 2;
    int lane = tid & 31, wid = tid >> 5;
    int wm = wid & 3, wn = wid >> 2;
    int gid = lane >> 2, tig = lane & 3;
    int aRow = lane & 15, aCol = (lane < 16) ? 0 : 4;
    int r0 = wm * 16 + gid, r1 = r0 + 8;

    const float* qbase = qb + ((size_t)(b * TP + cs)) * DD + h * 64;
#pragma unroll
    for (int i = 0; i < 4; i++) {
        int e = tid + i * 256;
        int row = e >> 4, dq = (e & 15) * 4;
        float4 v = *(const float4*)(qbase + (size_t)row * DD + dq);
        Qs[row * 68 + dq + 0] = v.x; Qs[row * 68 + dq + 1] = v.y;
        Qs[row * 68 + dq + 2] = v.z; Qs[row * 68 + dq + 3] = v.w;
    }
    if (tid < 64) { rowm[tid] = NEGINF; rowsum[tid] = 0.f; }

    float accO[4][4];
#pragma unroll
    for (int i = 0; i < 4; i++)
#pragma unroll
        for (int j = 0; j < 4; j++) accO[i][j] = 0.f;

    size_t qr0 = ((size_t)(b * TP + cs + r0) * HH + h) * 383;
    size_t qr1 = ((size_t)(b * TP + cs + r1) * HH + h) * 383;

    __syncthreads();

    for (int pg = 0; pg < 9; pg++) {
        const float* kp = kv + ((size_t)(b * TP + pg * 128)) * 256 + g * 64;
#pragma unroll
        for (int i = 0; i < 8; i++) {
            int e = tid + i * 256;
            int row = e >> 4, dq = (e & 15) * 4;
            float4 kk = *(const float4*)(kp + (size_t)row * 256 + dq);
            Ks[row * 68 + dq + 0] = kk.x; Ks[row * 68 + dq + 1] = kk.y;
            Ks[row * 68 + dq + 2] = kk.z; Ks[row * 68 + dq + 3] = kk.w;
            float4 vv = *(const float4*)(kp + (size_t)row * 256 + 128 + dq);
            Vt[(dq + 0) * 132 + row] = vv.x; Vt[(dq + 1) * 132 + row] = vv.y;
            Vt[(dq + 2) * 132 + row] = vv.z; Vt[(dq + 3) * 132 + row] = vv.w;
        }
        __syncthreads();

        // S = Q @ K^T (warp tile 16 x 64)
        float accS[8][4];
#pragma unroll
        for (int i = 0; i < 8; i++)
#pragma unroll
            for (int j = 0; j < 4; j++) accS[i][j] = 0.f;
#pragma unroll
        for (int ks = 0; ks < 8; ks++) {
            int kk = ks * 8;
            unsigned a[4];
            ldm_x4(a[0], a[1], a[2], a[3], &Qs[(wm * 16 + aRow) * 68 + kk + aCol]);
#pragma unroll
            for (int ng = 0; ng < 2; ng++) {
                int n0 = wn * 64 + ng * 32;
                unsigned bL[4], bH[4];
                ldm_x4(bL[0], bL[1], bL[2], bL[3], &Ks[(n0 + lane) * 68 + kk]);
                ldm_x4(bH[0], bH[1], bH[2], bH[3], &Ks[(n0 + lane) * 68 + kk + 4]);
#pragma unroll
                for (int t2 = 0; t2 < 4; t2++) {
                    unsigned bb[2] = { bL[t2], bH[t2] };
                    mma_tf32(accS[ng * 4 + t2], a, bb);
                }
            }
        }
        // bias, spill to smem
#pragma unroll
        for (int nt = 0; nt < 8; nt++) {
            int c0 = wn * 64 + nt * 8 + tig * 2;
            int c1 = c0 + 1;
            int k0 = pg * 128 + c0, k1 = k0 + 1;
            int d00 = max(-191, min(191, cs + r0 - k0));
            int d01 = max(-191, min(191, cs + r0 - k1));
            int d10 = max(-191, min(191, cs + r1 - k0));
            int d11 = max(-191, min(191, cs + r1 - k1));
            S[r0 * 132 + c0] = accS[nt][0] + __ldg(&qrel[qr0 + 191 + d00]);
            S[r0 * 132 + c1] = accS[nt][1] + __ldg(&qrel[qr0 + 191 + d01]);
            S[r1 * 132 + c0] = accS[nt][2] + __ldg(&qrel[qr1 + 191 + d10]);
            S[r1 * 132 + c1] = accS[nt][3] + __ldg(&qrel[qr1 + 191 + d11]);
        }
        __syncthreads();

        // online softmax update (warp per 8 rows)
#pragma unroll
        for (int rw = 0; rw < 8; rw++) {
            int r = wid * 8 + rw;
            float v0 = S[r * 132 + lane];
            float v1 = S[r * 132 + lane + 32];
            float v2 = S[r * 132 + lane + 64];
            float v3 = S[r * 132 + lane + 96];
            float mn = fmaxf(fmaxf(v0, v1), fmaxf(v2, v3));
#pragma unroll
            for (int o = 16; o > 0; o >>= 1) mn = fmaxf(mn, __shfl_xor_sync(0xffffffffu, mn, o));
            float mo = rowm[r];
            float mp = fmaxf(mo, mn);
            float p0 = expf(v0 - mp), p1 = expf(v1 - mp), p2 = expf(v2 - mp), p3 = expf(v3 - mp);
            S[r * 132 + lane] = p0; S[r * 132 + lane + 32] = p1;
            S[r * 132 + lane + 64] = p2; S[r * 132 + lane + 96] = p3;
            float ss = p0 + p1 + p2 + p3;
#pragma unroll
            for (int o = 16; o > 0; o >>= 1) ss += __shfl_xor_sync(0xffffffffu, ss, o);
            if (lane == 0) {
                float scale = expf(mo - mp);
                rowm[r] = mp;
                rowscale[r] = scale;
                rowsum[r] = rowsum[r] * scale + ss;
            }
        }
        __syncthreads();

        // rescale accumulators, then PV via mma (k = 128)
        float sc0 = rowscale[r0], sc1 = rowscale[r1];
#pragma unroll
        for (int nt = 0; nt < 4; nt++) {
            accO[nt][0] *= sc0; accO[nt][1] *= sc0;
            accO[nt][2] *= sc1; accO[nt][3] *= sc1;
        }
#pragma unroll
        for (int ks = 0; ks < 16; ks++) {
            int kk = ks * 8;
            unsigned a[4], bL[4], bH[4];
            ldm_x4(a[0], a[1], a[2], a[3], &S[(wm * 16 + aRow) * 132 + kk + aCol]);
            ldm_x4(bL[0], bL[1], bL[2], bL[3], &Vt[(wn * 32 + lane) * 132 + kk]);
            ldm_x4(bH[0], bH[1], bH[2], bH[3], &Vt[(wn * 32 + lane) * 132 + kk + 4]);
#pragma unroll
            for (int nt = 0; nt < 4; nt++) {
                unsigned bb[2] = { bL[nt], bH[nt] };
                mma_tf32(accO[nt], a, bb);
            }
        }
        __syncthreads();
    }

    // store invalid rows only
    int q0 = cs + r0, q1 = cs + r1;
    float inv0 = 1.f / rowsum[r0];
    float inv1 = 1.f / rowsum[r1];
#pragma unroll
    for (int nt = 0; nt < 4; nt++) {
        int d0 = wn * 32 + nt * 8 + tig * 2;
        if (q0 >= lim) {
            float* op = ob + ((size_t)(b * TT + q0 - 128)) * DD + h * 64 + d0;
            op[0] = accO[nt][0] * inv0; op[1] = accO[nt][1] * inv0;
        }
        if (q1 >= lim) {
            float* op = ob + ((size_t)(b * TT + q1 - 128)) * DD + h * 64 + d0;
            op[0] = accO[nt][2] * inv1; op[1] = accO[nt][3] * inv1;
        }
    }
}

// ---------------- depthwise conv (k=9, pad 4) + SiLU ----------------
__global__ __launch_bounds__(128) void dwconv_silu(
    const float* __restrict__ in, const float* __restrict__ dw, float* __restrict__ out)
{
    int t = blockIdx.x, b = blockIdx.y;
    int d0 = threadIdx.x * 4;
    float w[9][4];
#pragma unroll
    for (int c = 0; c < 4; c++)
#pragma unroll
        for (int j = 0; j < 9; j++)
            w[j][c] = __ldg(&dw[(d0 + c) * 9 + j]);
    float4 acc = make_float4(0.f, 0.f, 0.f, 0.f);
#pragma unroll
    for (int j = 0; j < 9; j++) {
        int tt = t + j - 4;
        if (tt >= 0 && tt < TT) {
            float4 v = *(const float4*)(in + ((size_t)(b * TT + tt)) * DD + d0);
            acc.x += v.x * w[j][0];
            acc.y += v.y * w[j][1];
            acc.z += v.z * w[j][2];
            acc.w += v.w * w[j][3];
        }
    }
    acc.x = acc.x / (1.f + expf(-acc.x));
    acc.y = acc.y / (1.f + expf(-acc.y));
    acc.z = acc.z / (1.f + expf(-acc.z));
    acc.w = acc.w / (1.f + expf(-acc.w));
    *(float4*)(out + ((size_t)(b * TT + t)) * DD + d0) = acc;
}

// ---------------- orchestration ----------------
extern "C" void kernel_launch(void* const* d_in, const int* in_sizes, int n_in,
                              void* d_out, int out_size)
{
    const float* x_in  = (const float*)d_in[0];
    const int*   alen  = (const int*)d_in[1];
    const float* ln1_w = (const float*)d_in[2];
    const float* ln1_b = (const float*)d_in[3];
    const float* wq    = (const float*)d_in[4];
    const float* wk    = (const float*)d_in[5];
    const float* wv    = (const float*)d_in[6];
    const float* wo    = (const float*)d_in[7];
    const float* rel   = (const float*)d_in[8];
    const float* ln2_w = (const float*)d_in[9];
    const float* ln2_b = (const float*)d_in[10];
    const float* pw1   = (const float*)d_in[11];
    const float* dw    = (const float*)d_in[12];
    const float* pw2   = (const float*)d_in[13];
    const float* ln3_w = (const float*)d_in[14];
    const float* ln3_b = (const float*)d_in[15];
    const float* w1    = (const float*)d_in[16];
    const float* w2    = (const float*)d_in[17];

    float* scr = nullptr;
    cudaGetSymbolAddress((void**)&scr, g_scr);
    float* xpad  = scr + OFF_XPAD;
    float* xbuf  = scr + OFF_XBUF;
    float* ybuf  = scr + OFF_YBUF;
    float* qbuf  = scr + OFF_QBUF;
    float* kvbuf = scr + OFF_KVBUF;
    float* qrlb  = scr + OFF_QREL;
    float* obuf  = scr + OFF_OBUF;
    float* hbuf  = scr + OFF_HBUF;
    float* gbuf  = scr + OFF_GBUF;
    float* kvw   = scr + OFF_KVW;
    float* pw1p  = scr + OFF_PW1P;
    float* w1p   = scr + OFF_W1P;

    const int WIN_SMEM = (64 * 68 + 192 * 68 + 64 * 196 + 64 * 196) * 4;            // 169984
    const int DF_SMEM  = (64 * 68 + 128 * 68 + 64 * 132 + 64 * 132 + 192) * 4;      // 120576
    cudaFuncSetAttribute(win_attn, cudaFuncAttributeMaxDynamicSharedMemorySize, WIN_SMEM);
    cudaFuncSetAttribute(dense_flash, cudaFuncAttributeMaxDynamicSharedMemorySize, DF_SMEM);

    zero_pad_kernel<<<(BB * LCW * DD + 255) / 256, 256>>>(xpad);
    pack_kv<<<(4 * 256 * 512 + 255) / 256, 256>>>(wk, wv, kvw);
    pack_glu<<<(4 * 1024 * 512 + 255) / 256, 256>>>(pw1, pw1p, 512, 4 * 1024 * 512);
    pack_glu<<<(4 * 2048 * 512 + 255) / 256, 256>>>(w1, w1p, 1024, 4 * 2048 * 512);

    for (int l = 0; l < 4; l++) {
        const float* src = (l == 0) ? x_in : xbuf;
        ln_kernel<<<4096, 128>>>(src, ln1_w + l * 512, ln1_b + l * 512, ybuf, xpad);
        gemm_tc<<<dim3(8, 36), 256>>>(xpad, wq + (size_t)l * 512 * 512, qbuf, nullptr, 4608, 512, 512, 0.125f, 0);
        gemm_tc<<<dim3(4, 36), 256>>>(xpad, kvw + (size_t)l * 256 * 512, kvbuf, nullptr, 4608, 256, 512, 1.f, 0);
        gemm_tc<<<dim3(6, 288), 256>>>(qbuf, rel + (size_t)l * 383 * 64, qrlb, nullptr, 36864, 383, 64, 1.f, 0);
        win_attn<<<dim3(16, 8, 4), 256, WIN_SMEM>>>(qbuf, kvbuf, qrlb, alen, obuf);
        dense_flash<<<dim3(16, 8, 4), 256, DF_SMEM>>>(qbuf, kvbuf, qrlb, alen, obuf);
        gemm_tc<<<dim3(8, 32), 256>>>(obuf, wo + (size_t)l * 512 * 512, xbuf, ybuf, 4096, 512, 512, 1.f, 0);
        ln_kernel<<<4096, 128>>>(xbuf, ln2_w + l * 512, ln2_b + l * 512, ybuf, nullptr);
        gemm_tc<<<dim3(16, 32), 256>>>(ybuf, pw1p + (size_t)l * 1024 * 512, gbuf, nullptr, 4096, 1024, 512, 1.f, 1);
        dwconv_silu<<<dim3(1024, 4), 128>>>(gbuf, dw + (size_t)l * 512 * 9, hbuf);
        gemm_tc<<<dim3(8, 32), 256>>>(hbuf, pw2 + (size_t)l * 512 * 512, xbuf, ybuf, 4096, 512, 512, 1.f, 0);
        ln_kernel<<<4096, 128>>>(xbuf, ln3_w + l * 512, ln3_b + l * 512, ybuf, nullptr);
        gemm_tc<<<dim3(32, 32), 256>>>(ybuf, w1p + (size_t)l * 2048 * 512, gbuf, nullptr, 4096, 2048, 512, 1.f, 2);
        float* dst = (l == 3) ? (float*)d_out : xbuf;
        gemm_tc<<<dim3(8, 32), 256>>>(gbuf, w2 + (size_t)l * 512 * 1024, dst, ybuf, 4096, 512, 1024, 1.f, 0);
    }
}